// round 13
// baseline (speedup 1.0000x reference)
#include <cuda_runtime.h>
#include <cuda_bf16.h>
#include <cstdint>
#include <math.h>

// ---------------- problem constants ----------------
#define BB  2
#define TT  2048
#define DD  2048
#define NHH 16
#define HDD 128
#define MM  (BB*TT)
#define ELEMS ((long)BB*TT*DD)
#define ESZ ((long)BB*NHH*TT*TT)

// GEMM tiling
#define GBM 128
#define GBN 128
#define GBK 32
#define GTHREADS 256

// SMEM: per stage 4 halves (AH, AL, BH, BL), 128 rows x 80B pitch each
#define PITCH 80
#define HALF_SZ 10240
#define STG 40960
#define NSTAGE 2
#define GEMM_SMEM (NSTAGE*STG)   // 81920 bytes -> 2 CTAs/SM

// epilogue modes (bitmask)
#define EPI_C      1   // write fp32 C (+resid fp32)
#define EPI_SPLIT  2   // write split bf16 OH/OL of val
#define EPI_SWIGLU 4   // r = RH+RL; val = r*sigmoid(r)*val

// ---------------- scratch (static device memory) ----------------
__device__ __nv_bfloat16 g_nH[ELEMS], g_nL[ELEMS];
__device__ __nv_bfloat16 g_qkvH[3*ELEMS], g_qkvL[3*ELEMS];
__device__ __nv_bfloat16 g_vTH[ELEMS], g_vTL[ELEMS];
__device__ __nv_bfloat16 g_ctxH[ELEMS], g_ctxL[ELEMS];
__device__ float g_h2[ELEMS];
__device__ __nv_bfloat16 g_x1H[ELEMS], g_x1L[ELEMS];
__device__ __nv_bfloat16 g_gH[ELEMS], g_gL[ELEMS];
__device__ __nv_bfloat16 g_wH[7L*DD*DD], g_wL[7L*DD*DD];
__device__ __nv_bfloat16 g_eH[ESZ], g_eL[ESZ];
__device__ __nv_bfloat16 g_pH[ESZ], g_pL[ESZ];

// ---------------- helpers ----------------
__device__ __forceinline__ uint32_t smem_u32(const void* p) {
    uint32_t a;
    asm("{ .reg .u64 t; cvta.to.shared.u64 t, %1; cvt.u32.u64 %0, t; }" : "=r"(a) : "l"(p));
    return a;
}
__device__ __forceinline__ void ldsm4(uint32_t* r, uint32_t addr) {
    asm volatile("ldmatrix.sync.aligned.m8n8.x4.shared.b16 {%0,%1,%2,%3}, [%4];"
        : "=r"(r[0]), "=r"(r[1]), "=r"(r[2]), "=r"(r[3]) : "r"(addr));
}
__device__ __forceinline__ void mma_bf16(float* c, const uint32_t* a, const uint32_t* b) {
    asm volatile(
        "mma.sync.aligned.m16n8k16.row.col.f32.bf16.bf16.f32 "
        "{%0,%1,%2,%3}, {%4,%5,%6,%7}, {%8,%9}, {%0,%1,%2,%3};"
        : "+f"(c[0]), "+f"(c[1]), "+f"(c[2]), "+f"(c[3])
        : "r"(a[0]), "r"(a[1]), "r"(a[2]), "r"(a[3]), "r"(b[0]), "r"(b[1]));
}
__device__ __forceinline__ void cpasync16(uint32_t dst, const void* src) {
    asm volatile("cp.async.cg.shared.global [%0], [%1], 16;" :: "r"(dst), "l"(src));
}
#define CP_COMMIT() asm volatile("cp.async.commit_group;" ::: "memory")
#define CP_WAIT(N)  asm volatile("cp.async.wait_group %0;" :: "n"(N) : "memory")

__device__ __forceinline__ void split1(float v, __nv_bfloat16& h, __nv_bfloat16& l) {
    h = __float2bfloat16(v);
    l = __float2bfloat16(v - __bfloat162float(h));
}
// reconstruct 8 fp32 from hi/lo bf16x8 (two uint4)
__device__ __forceinline__ void bf2f8(uint4 uh, uint4 ul, float* e) {
    const __nv_bfloat162* h2 = (const __nv_bfloat162*)&uh;
    const __nv_bfloat162* l2 = (const __nv_bfloat162*)&ul;
    #pragma unroll
    for (int p = 0; p < 4; p++) {
        float2 a = __bfloat1622float2(h2[p]);
        float2 b = __bfloat1622float2(l2[p]);
        e[2*p]   = a.x + b.x;
        e[2*p+1] = a.y + b.y;
    }
}

// ---------------- bf16-split GEMM (2-stage cp.async pipeline, 2 CTAs/SM) ----------------
__global__ __launch_bounds__(GTHREADS, 2) void gemm_bf16s(
    const __nv_bfloat16* __restrict__ AH, const __nv_bfloat16* __restrict__ AL,
    const __nv_bfloat16* __restrict__ BH, const __nv_bfloat16* __restrict__ BL,
    const float* __restrict__ bias, const float* __restrict__ bias2, const float* __restrict__ bias3,
    const float* __restrict__ resid,
    const __nv_bfloat16* __restrict__ RH, const __nv_bfloat16* __restrict__ RL,
    float* __restrict__ C, __nv_bfloat16* __restrict__ OH, __nv_bfloat16* __restrict__ OL,
    int K, int lda, int ldb, int ldc,
    long sAb, long sAh, long sBb, long sBh, long sCb, long sCh, int nh,
    float alpha, int mode)
{
    extern __shared__ char smem[];
    const uint32_t sbase = smem_u32(smem);
    const int tid = threadIdx.x;
    const int wid = tid >> 5;
    const int lane = tid & 31;

    int z = blockIdx.z;
    int bz = z / nh, hz = z % nh;
    const long aoff = (long)bz * sAb + (long)hz * sAh;
    const long boff = (long)bz * sBb + (long)hz * sBh;
    const long coff = (long)bz * sCb + (long)hz * sCh;
    AH += aoff; AL += aoff;
    BH += boff; BL += boff;

    const float* bb = bias;
    if (bias2) bb = (hz == 0) ? bias : ((hz == 1) ? bias2 : bias3);

    const int bm = blockIdx.y * GBM;
    const int bn = blockIdx.x * GBN;

    const int wm = wid >> 2;
    const int wn = wid & 3;

    const uint32_t aOff = (uint32_t)(wm * 64 + (lane & 15)) * PITCH + (lane >> 4) * 16;
    const uint32_t bOff = 2 * HALF_SZ
        + (uint32_t)(wn * 32 + ((lane >> 4) << 3) + (lane & 7)) * PITCH + ((lane >> 3) & 1) * 16;

    const int cid0 = tid * 2, cid1 = cid0 + 1;
    const int r0 = cid0 >> 2, c0 = cid0 & 3;
    const int r1 = cid1 >> 2, c1 = cid1 & 3;
    const __nv_bfloat16* aH0 = AH + (long)(bm + r0) * lda + c0 * 8;
    const __nv_bfloat16* aH1 = AH + (long)(bm + r1) * lda + c1 * 8;
    const __nv_bfloat16* aL0 = AL + (long)(bm + r0) * lda + c0 * 8;
    const __nv_bfloat16* aL1 = AL + (long)(bm + r1) * lda + c1 * 8;
    const __nv_bfloat16* bH0 = BH + (long)(bn + r0) * ldb + c0 * 8;
    const __nv_bfloat16* bH1 = BH + (long)(bn + r1) * ldb + c1 * 8;
    const __nv_bfloat16* bL0 = BL + (long)(bn + r0) * ldb + c0 * 8;
    const __nv_bfloat16* bL1 = BL + (long)(bn + r1) * ldb + c1 * 8;
    const uint32_t d0 = (uint32_t)(r0 * PITCH + c0 * 16);
    const uint32_t d1 = (uint32_t)(r1 * PITCH + c1 * 16);

#define ISSUE_STAGE(SIDX, KO) do {                                   \
        uint32_t s_ = sbase + (uint32_t)(SIDX) * STG;                \
        long ko_ = (KO);                                             \
        cpasync16(s_ + d0,             aH0 + ko_);                   \
        cpasync16(s_ + d1,             aH1 + ko_);                   \
        cpasync16(s_ + HALF_SZ + d0,   aL0 + ko_);                   \
        cpasync16(s_ + HALF_SZ + d1,   aL1 + ko_);                   \
        cpasync16(s_ + 2*HALF_SZ + d0, bH0 + ko_);                   \
        cpasync16(s_ + 2*HALF_SZ + d1, bH1 + ko_);                   \
        cpasync16(s_ + 3*HALF_SZ + d0, bL0 + ko_);                   \
        cpasync16(s_ + 3*HALF_SZ + d1, bL1 + ko_);                   \
    } while (0)

    float acc[4][4][4];
    #pragma unroll
    for (int i = 0; i < 4; i++)
        #pragma unroll
        for (int j = 0; j < 4; j++)
            #pragma unroll
            for (int r = 0; r < 4; r++) acc[i][j][r] = 0.f;

    const int NKI = K / GBK;

    // prologue: issue stage 0
    ISSUE_STAGE(0, 0L);
    CP_COMMIT();

    for (int i = 0; i < NKI; i++) {
        CP_WAIT(0);
        __syncthreads();

        if (i + 1 < NKI) ISSUE_STAGE((i + 1) & (NSTAGE - 1), (long)(i + 1) * GBK);
        CP_COMMIT();

        const uint32_t sb = sbase + (uint32_t)(i & (NSTAGE - 1)) * STG;
        #pragma unroll
        for (int ks = 0; ks < 2; ks++) {
            uint32_t afh[4][4], afl[4][4];
            uint32_t bfh[2][4], bfl[2][4];
            #pragma unroll
            for (int mf = 0; mf < 4; mf++) {
                uint32_t ad = sb + aOff + mf * (16 * PITCH) + ks * 32;
                ldsm4(afh[mf], ad);
                ldsm4(afl[mf], ad + HALF_SZ);
            }
            #pragma unroll
            for (int np = 0; np < 2; np++) {
                uint32_t bd = sb + bOff + np * (16 * PITCH) + ks * 32;
                ldsm4(bfh[np], bd);
                ldsm4(bfl[np], bd + HALF_SZ);
            }
            #pragma unroll
            for (int mf = 0; mf < 4; mf++) {
                #pragma unroll
                for (int nf = 0; nf < 4; nf++) {
                    const int np = nf >> 1;
                    const int pr = (nf & 1) * 2;
                    mma_bf16(acc[mf][nf], afh[mf], &bfh[np][pr]);
                    mma_bf16(acc[mf][nf], afh[mf], &bfl[np][pr]);
                    mma_bf16(acc[mf][nf], afl[mf], &bfh[np][pr]);
                }
            }
        }
        __syncthreads();
    }
#undef ISSUE_STAGE

    float* Cp = C ? C + coff : nullptr;
    __nv_bfloat16* OHp = OH ? OH + coff : nullptr;
    __nv_bfloat16* OLp = OL ? OL + coff : nullptr;
    const int g = lane >> 2;
    const int t = lane & 3;
    #pragma unroll
    for (int mf = 0; mf < 4; mf++) {
        #pragma unroll
        for (int nf = 0; nf < 4; nf++) {
            int row0 = bm + wm * 64 + mf * 16 + g;
            int col = bn + wn * 32 + nf * 8 + t * 2;
            float2 v0, v1;
            v0.x = acc[mf][nf][0] * alpha;
            v0.y = acc[mf][nf][1] * alpha;
            v1.x = acc[mf][nf][2] * alpha;
            v1.y = acc[mf][nf][3] * alpha;
            if (bb) {
                float2 bbv = *(const float2*)(bb + col);
                v0.x += bbv.x; v0.y += bbv.y;
                v1.x += bbv.x; v1.y += bbv.y;
            }
            long o0 = (long)row0 * ldc + col;
            long o1 = (long)(row0 + 8) * ldc + col;
            if (mode & EPI_SWIGLU) {
                // r = RH+RL (bf16 split of x1); val = r*sigmoid(r)*val
                float2 a0 = __bfloat1622float2(*(const __nv_bfloat162*)(RH + o0));
                float2 b0 = __bfloat1622float2(*(const __nv_bfloat162*)(RL + o0));
                float2 a1 = __bfloat1622float2(*(const __nv_bfloat162*)(RH + o1));
                float2 b1 = __bfloat1622float2(*(const __nv_bfloat162*)(RL + o1));
                float rx0 = a0.x + b0.x, ry0 = a0.y + b0.y;
                float rx1 = a1.x + b1.x, ry1 = a1.y + b1.y;
                v0.x = rx0 * (1.0f / (1.0f + expf(-rx0))) * v0.x;
                v0.y = ry0 * (1.0f / (1.0f + expf(-ry0))) * v0.y;
                v1.x = rx1 * (1.0f / (1.0f + expf(-rx1))) * v1.x;
                v1.y = ry1 * (1.0f / (1.0f + expf(-ry1))) * v1.y;
            }
            if (mode & EPI_SPLIT) {
                __nv_bfloat162 h0, l0, h1, l1;
                split1(v0.x, h0.x, l0.x); split1(v0.y, h0.y, l0.y);
                split1(v1.x, h1.x, l1.x); split1(v1.y, h1.y, l1.y);
                *(__nv_bfloat162*)(OHp + o0) = h0;
                *(__nv_bfloat162*)(OLp + o0) = l0;
                *(__nv_bfloat162*)(OHp + o1) = h1;
                *(__nv_bfloat162*)(OLp + o1) = l1;
            }
            if (mode & EPI_C) {
                if (resid) {
                    float2 rr0 = *(const float2*)(resid + o0);
                    float2 rr1 = *(const float2*)(resid + o1);
                    v0.x += rr0.x; v0.y += rr0.y;
                    v1.x += rr1.x; v1.y += rr1.y;
                }
                *(float2*)(Cp + o0) = v0;
                *(float2*)(Cp + o1) = v1;
            }
        }
    }
}

// ---------------- transpose + split (fp32 input) ----------------
__global__ __launch_bounds__(256) void transpose_split(
    const float* __restrict__ in, __nv_bfloat16* __restrict__ oH, __nv_bfloat16* __restrict__ oL,
    int ldin, int ldout, long sInB, long sInH, long sOutB, long sOutH, int nh)
{
    __shared__ float tile[32][33];
    int z = blockIdx.z, bz = z / nh, hz = z % nh;
    in += (long)bz * sInB + (long)hz * sInH;
    long ob = (long)bz * sOutB + (long)hz * sOutH;
    oH += ob; oL += ob;
    int c0 = blockIdx.x << 5, r0 = blockIdx.y << 5;
    int tx = threadIdx.x & 31, ty = threadIdx.x >> 5;
    #pragma unroll
    for (int j = 0; j < 4; j++)
        tile[ty + j * 8][tx] = in[(long)(r0 + ty + j * 8) * ldin + c0 + tx];
    __syncthreads();
    #pragma unroll
    for (int j = 0; j < 4; j++) {
        float val = tile[tx][ty + j * 8];
        __nv_bfloat16 h, l;
        split1(val, h, l);
        long o = (long)(c0 + ty + j * 8) * ldout + r0 + tx;
        oH[o] = h; oL[o] = l;
    }
}

// ---------------- transpose + split (bf16 hi/lo input) ----------------
__global__ __launch_bounds__(256) void transpose_split_bf2(
    const __nv_bfloat16* __restrict__ inH, const __nv_bfloat16* __restrict__ inL,
    __nv_bfloat16* __restrict__ oH, __nv_bfloat16* __restrict__ oL,
    int ldin, int ldout, long sInB, long sInH, long sOutB, long sOutH, int nh)
{
    __shared__ float tile[32][33];
    int z = blockIdx.z, bz = z / nh, hz = z % nh;
    long ib = (long)bz * sInB + (long)hz * sInH;
    inH += ib; inL += ib;
    long ob = (long)bz * sOutB + (long)hz * sOutH;
    oH += ob; oL += ob;
    int c0 = blockIdx.x << 5, r0 = blockIdx.y << 5;
    int tx = threadIdx.x & 31, ty = threadIdx.x >> 5;
    #pragma unroll
    for (int j = 0; j < 4; j++) {
        long idx = (long)(r0 + ty + j * 8) * ldin + c0 + tx;
        tile[ty + j * 8][tx] = __bfloat162float(inH[idx]) + __bfloat162float(inL[idx]);
    }
    __syncthreads();
    #pragma unroll
    for (int j = 0; j < 4; j++) {
        float val = tile[tx][ty + j * 8];
        __nv_bfloat16 h, l;
        split1(val, h, l);
        long o = (long)(c0 + ty + j * 8) * ldout + r0 + tx;
        oH[o] = h; oL[o] = l;
    }
}

// ---------------- block reductions ----------------
__device__ __forceinline__ float block_reduce_sum(float v) {
    __shared__ float sh[8];
    #pragma unroll
    for (int o = 16; o > 0; o >>= 1) v += __shfl_xor_sync(0xffffffffu, v, o);
    int w = threadIdx.x >> 5;
    if ((threadIdx.x & 31) == 0) sh[w] = v;
    __syncthreads();
    if (threadIdx.x < 8) {
        v = sh[threadIdx.x];
        #pragma unroll
        for (int o = 4; o > 0; o >>= 1) v += __shfl_xor_sync(0xffu, v, o);
        if (threadIdx.x == 0) sh[0] = v;
    }
    __syncthreads();
    float r = sh[0];
    __syncthreads();
    return r;
}
__device__ __forceinline__ float block_reduce_max(float v) {
    __shared__ float sh[8];
    #pragma unroll
    for (int o = 16; o > 0; o >>= 1) v = fmaxf(v, __shfl_xor_sync(0xffffffffu, v, o));
    int w = threadIdx.x >> 5;
    if ((threadIdx.x & 31) == 0) sh[w] = v;
    __syncthreads();
    if (threadIdx.x < 8) {
        v = sh[threadIdx.x];
        #pragma unroll
        for (int o = 4; o > 0; o >>= 1) v = fmaxf(v, __shfl_xor_sync(0xffu, v, o));
        if (threadIdx.x == 0) sh[0] = v;
    }
    __syncthreads();
    float r = sh[0];
    __syncthreads();
    return r;
}

// ---------------- RMSNorm -> split bf16 ----------------
__global__ __launch_bounds__(256) void rmsnorm_split(
    const float* __restrict__ x, const float* __restrict__ scale,
    __nv_bfloat16* __restrict__ yH, __nv_bfloat16* __restrict__ yL)
{
    long row = blockIdx.x;
    const float* xr = x + row * (long)DD;
    float vals[8];
    float ss = 0.f;
    #pragma unroll
    for (int i = 0; i < 8; i++) {
        int idx = threadIdx.x + i * 256;
        float v = xr[idx];
        vals[i] = v;
        ss += v * v;
    }
    ss = block_reduce_sum(ss);
    float r = rsqrtf(ss * (1.0f / DD) + 1e-5f);
    long base = row * (long)DD;
    #pragma unroll
    for (int i = 0; i < 8; i++) {
        int idx = threadIdx.x + i * 256;
        float v = scale[idx] * vals[i] * r;
        __nv_bfloat16 h, l;
        split1(v, h, l);
        yH[base + idx] = h; yL[base + idx] = l;
    }
}

// ---------------- softmax over split-bf16 energy -> split bf16 probs ----------------
__global__ __launch_bounds__(256) void softmax_split(
    const __nv_bfloat16* __restrict__ eH, const __nv_bfloat16* __restrict__ eL,
    __nv_bfloat16* __restrict__ pH, __nv_bfloat16* __restrict__ pL)
{
    long base = (long)blockIdx.x * TT;
    // 2048 elems / 256 threads = 8 per thread (one uint4 of H + one of L)
    uint4 uh = *(const uint4*)(eH + base + threadIdx.x * 8);
    uint4 ul = *(const uint4*)(eL + base + threadIdx.x * 8);
    float e[8];
    bf2f8(uh, ul, e);
    float m = e[0];
    #pragma unroll
    for (int j = 1; j < 8; j++) m = fmaxf(m, e[j]);
    m = block_reduce_max(m);
    float s = 0.f;
    #pragma unroll
    for (int j = 0; j < 8; j++) {
        e[j] = expf(e[j] - m);
        s += e[j];
    }
    s = block_reduce_sum(s);
    float inv = 1.0f / s;
    uint32_t oh[4], ol[4];
    #pragma unroll
    for (int p = 0; p < 4; p++) {
        __nv_bfloat16 h0, l0, h1, l1;
        split1(e[2*p]   * inv, h0, l0);
        split1(e[2*p+1] * inv, h1, l1);
        __nv_bfloat162 hp = __halves2bfloat162(h0, h1);
        __nv_bfloat162 lp = __halves2bfloat162(l0, l1);
        oh[p] = *(uint32_t*)&hp;
        ol[p] = *(uint32_t*)&lp;
    }
    *(uint4*)(pH + base + threadIdx.x * 8) = make_uint4(oh[0], oh[1], oh[2], oh[3]);
    *(uint4*)(pL + base + threadIdx.x * 8) = make_uint4(ol[0], ol[1], ol[2], ol[3]);
}

// ---------------- launcher ----------------
extern "C" void kernel_launch(void* const* d_in, const int* in_sizes, int n_in,
                              void* d_out, int out_size) {
    const float* x      = (const float*)d_in[0];
    const float* Wq     = (const float*)d_in[1];
    const float* bq     = (const float*)d_in[2];
    const float* Wk     = (const float*)d_in[3];
    const float* bk     = (const float*)d_in[4];
    const float* Wv     = (const float*)d_in[5];
    const float* bv     = (const float*)d_in[6];
    const float* Wo     = (const float*)d_in[7];
    const float* bo     = (const float*)d_in[8];
    const float* scale1 = (const float*)d_in[9];
    const float* scale2 = (const float*)d_in[10];
    const float* W1     = (const float*)d_in[11];
    const float* W2     = (const float*)d_in[12];
    const float* W3     = (const float*)d_in[13];
    float* out = (float*)d_out;

    __nv_bfloat16 *nH, *nL, *qkvH, *qkvL, *vTH, *vTL, *ctxH, *ctxL;
    __nv_bfloat16 *x1H, *x1L, *gH, *gL, *wH, *wL, *eH, *eL, *pH, *pL;
    float *h2;
    cudaGetSymbolAddress((void**)&nH, g_nH);     cudaGetSymbolAddress((void**)&nL, g_nL);
    cudaGetSymbolAddress((void**)&qkvH, g_qkvH); cudaGetSymbolAddress((void**)&qkvL, g_qkvL);
    cudaGetSymbolAddress((void**)&vTH, g_vTH);   cudaGetSymbolAddress((void**)&vTL, g_vTL);
    cudaGetSymbolAddress((void**)&ctxH, g_ctxH); cudaGetSymbolAddress((void**)&ctxL, g_ctxL);
    cudaGetSymbolAddress((void**)&h2, g_h2);
    cudaGetSymbolAddress((void**)&x1H, g_x1H);   cudaGetSymbolAddress((void**)&x1L, g_x1L);
    cudaGetSymbolAddress((void**)&gH, g_gH);     cudaGetSymbolAddress((void**)&gL, g_gL);
    cudaGetSymbolAddress((void**)&wH, g_wH);     cudaGetSymbolAddress((void**)&wL, g_wL);
    cudaGetSymbolAddress((void**)&eH, g_eH);     cudaGetSymbolAddress((void**)&eL, g_eL);
    cudaGetSymbolAddress((void**)&pH, g_pH);     cudaGetSymbolAddress((void**)&pL, g_pL);

    cudaFuncSetAttribute(gemm_bf16s, cudaFuncAttributeMaxDynamicSharedMemorySize, GEMM_SMEM);

    const float inv_sqrt_hd = 0.08838834764831845f;
    const long DSQ = (long)DD * DD;
    __nv_bfloat16 *WoH = wH + 3*DSQ, *WoL = wL + 3*DSQ;
    __nv_bfloat16 *W1H = wH + 4*DSQ, *W1L = wL + 4*DSQ;
    __nv_bfloat16 *W2H = wH + 5*DSQ, *W2L = wL + 5*DSQ;
    __nv_bfloat16 *W3H = wH + 6*DSQ, *W3L = wL + 6*DSQ;

    // 0. transpose + split weights to [N][K] bf16 hi/lo (q,k,v contiguous slices 0..2)
    dim3 tgridW(DD / 32, DD / 32, 1);
    transpose_split<<<tgridW, 256>>>(Wq, wH + 0*DSQ, wL + 0*DSQ, DD, DD, 0, 0, 0, 0, 1);
    transpose_split<<<tgridW, 256>>>(Wk, wH + 1*DSQ, wL + 1*DSQ, DD, DD, 0, 0, 0, 0, 1);
    transpose_split<<<tgridW, 256>>>(Wv, wH + 2*DSQ, wL + 2*DSQ, DD, DD, 0, 0, 0, 0, 1);
    transpose_split<<<tgridW, 256>>>(Wo, WoH, WoL, DD, DD, 0, 0, 0, 0, 1);
    transpose_split<<<tgridW, 256>>>(W1, W1H, W1L, DD, DD, 0, 0, 0, 0, 1);
    transpose_split<<<tgridW, 256>>>(W2, W2H, W2L, DD, DD, 0, 0, 0, 0, 1);
    transpose_split<<<tgridW, 256>>>(W3, W3H, W3L, DD, DD, 0, 0, 0, 0, 1);

    dim3 gridDense(DD / GBN, MM / GBM, 1);
    dim3 gridQKV(DD / GBN, MM / GBM, 3);
    dim3 gridQK(TT / GBN, TT / GBM, BB * NHH);
    dim3 gridPV(1, TT / GBM, BB * NHH);

    // 1. norm1
    rmsnorm_split<<<MM, 256>>>(x, scale1, nH, nL);

    // 2. Q/K/V projections in ONE launch
    gemm_bf16s<<<gridQKV, GTHREADS, GEMM_SMEM>>>(nH, nL, wH, wL, bq, bk, bv, nullptr,
        nullptr, nullptr,
        nullptr, qkvH, qkvL, DD, DD, DD, DD,
        0, 0, 0, DSQ, 0, ELEMS, 3, 1.0f, EPI_SPLIT);

    // 3. vT split: [b,h][d][t] from V slice (z=2)
    dim3 tgridV(HDD / 32, TT / 32, BB * NHH);
    transpose_split_bf2<<<tgridV, 256>>>(qkvH + 2*ELEMS, qkvL + 2*ELEMS, vTH, vTL,
        DD, TT,
        (long)TT * DD, (long)HDD,
        (long)NHH * HDD * TT, (long)HDD * TT, NHH);

    // 4. energy = Q K^T / sqrt(HD)  -> split bf16
    gemm_bf16s<<<gridQK, GTHREADS, GEMM_SMEM>>>(qkvH, qkvL, qkvH + ELEMS, qkvL + ELEMS,
        nullptr, nullptr, nullptr, nullptr,
        nullptr, nullptr,
        nullptr, eH, eL,
        HDD, DD, DD, TT,
        (long)TT * DD, (long)HDD,
        (long)TT * DD, (long)HDD,
        (long)NHH * TT * TT, (long)TT * TT,
        NHH, inv_sqrt_hd, EPI_SPLIT);

    // 5. softmax (bf16-split in) -> split probs
    softmax_split<<<BB * NHH * TT, 256>>>(eH, eL, pH, pL);

    // 6. ctx = P @ V
    gemm_bf16s<<<gridPV, GTHREADS, GEMM_SMEM>>>(pH, pL, vTH, vTL,
        nullptr, nullptr, nullptr, nullptr,
        nullptr, nullptr,
        nullptr, ctxH, ctxL,
        TT, TT, TT, DD,
        (long)NHH * TT * TT, (long)TT * TT,
        (long)NHH * HDD * TT, (long)HDD * TT,
        (long)TT * DD, (long)HDD,
        NHH, 1.0f, EPI_SPLIT);

    // 7. h2 = ctx @ Wo + bo + x
    gemm_bf16s<<<gridDense, GTHREADS, GEMM_SMEM>>>(ctxH, ctxL, WoH, WoL, bo, nullptr, nullptr, x,
        nullptr, nullptr,
        h2, nullptr, nullptr, DD, DD, DD, DD, 0,0,0,0,0,0, 1, 1.0f, EPI_C);

    // 8. norm2
    rmsnorm_split<<<MM, 256>>>(h2, scale2, nH, nL);

    // 9. x1 = norm @ W1 (split only, no fp32 copy)
    gemm_bf16s<<<gridDense, GTHREADS, GEMM_SMEM>>>(nH, nL, W1H, W1L, nullptr, nullptr, nullptr, nullptr,
        nullptr, nullptr,
        nullptr, x1H, x1L, DD, DD, DD, DD, 0,0,0,0,0,0, 1, 1.0f, EPI_SPLIT);

    // 10+11. x2 = x1 @ W2 with fused swiglu (x1 reconstructed from split): g -> split
    gemm_bf16s<<<gridDense, GTHREADS, GEMM_SMEM>>>(x1H, x1L, W2H, W2L, nullptr, nullptr, nullptr, nullptr,
        x1H, x1L,
        nullptr, gH, gL, DD, DD, DD, DD, 0,0,0,0,0,0, 1, 1.0f, EPI_SWIGLU | EPI_SPLIT);

    // 12. out = g @ W3 + x
    gemm_bf16s<<<gridDense, GTHREADS, GEMM_SMEM>>>(gH, gL, W3H, W3L, nullptr, nullptr, nullptr, x,
        nullptr, nullptr,
        out, nullptr, nullptr, DD, DD, DD, DD, 0,0,0,0,0,0, 1, 1.0f, EPI_C);
}

// round 14
// speedup vs baseline: 1.0152x; 1.0152x over previous
#include <cuda_runtime.h>
#include <cuda_bf16.h>
#include <cstdint>
#include <math.h>

// ---------------- problem constants ----------------
#define BB  2
#define TT  2048
#define DD  2048
#define NHH 16
#define HDD 128
#define MM  (BB*TT)
#define ELEMS ((long)BB*TT*DD)
#define ESZ ((long)BB*NHH*TT*TT)

// GEMM tiling
#define GBM 128
#define GBN 128
#define GBK 32
#define GTHREADS 256

// SMEM: per stage 4 halves (AH, AL, BH, BL), 128 rows x 80B pitch each
#define PITCH 80
#define HALF_SZ 10240
#define STG 40960
#define NSTAGE 2
#define GEMM_SMEM (NSTAGE*STG)   // 81920 bytes -> 2 CTAs/SM

// epilogue modes (bitmask)
#define EPI_C      1   // write fp32 C (+resid)
#define EPI_SPLIT  2   // write split bf16 OH/OL of val
#define EPI_SWIGLU 4   // val = resid*sigmoid(resid)*val, then split write

// ---------------- scratch (static device memory) ----------------
__device__ __nv_bfloat16 g_nH[ELEMS], g_nL[ELEMS];
__device__ __nv_bfloat16 g_qkvH[3*ELEMS], g_qkvL[3*ELEMS];
__device__ __nv_bfloat16 g_vTH[ELEMS], g_vTL[ELEMS];
__device__ __nv_bfloat16 g_ctxH[ELEMS], g_ctxL[ELEMS];
__device__ float g_h2[ELEMS];
__device__ float g_x1[ELEMS];
__device__ __nv_bfloat16 g_x1H[ELEMS], g_x1L[ELEMS];
__device__ __nv_bfloat16 g_gH[ELEMS], g_gL[ELEMS];
__device__ __nv_bfloat16 g_wH[7L*DD*DD], g_wL[7L*DD*DD];
__device__ float g_energy[ESZ];
__device__ __nv_bfloat16 g_pH[ESZ], g_pL[ESZ];

// ---------------- helpers ----------------
__device__ __forceinline__ uint32_t smem_u32(const void* p) {
    uint32_t a;
    asm("{ .reg .u64 t; cvta.to.shared.u64 t, %1; cvt.u32.u64 %0, t; }" : "=r"(a) : "l"(p));
    return a;
}
__device__ __forceinline__ void ldsm4(uint32_t* r, uint32_t addr) {
    asm volatile("ldmatrix.sync.aligned.m8n8.x4.shared.b16 {%0,%1,%2,%3}, [%4];"
        : "=r"(r[0]), "=r"(r[1]), "=r"(r[2]), "=r"(r[3]) : "r"(addr));
}
__device__ __forceinline__ void mma_bf16(float* c, const uint32_t* a, const uint32_t* b) {
    asm volatile(
        "mma.sync.aligned.m16n8k16.row.col.f32.bf16.bf16.f32 "
        "{%0,%1,%2,%3}, {%4,%5,%6,%7}, {%8,%9}, {%0,%1,%2,%3};"
        : "+f"(c[0]), "+f"(c[1]), "+f"(c[2]), "+f"(c[3])
        : "r"(a[0]), "r"(a[1]), "r"(a[2]), "r"(a[3]), "r"(b[0]), "r"(b[1]));
}
__device__ __forceinline__ void cpasync16(uint32_t dst, const void* src) {
    asm volatile("cp.async.cg.shared.global [%0], [%1], 16;" :: "r"(dst), "l"(src));
}
#define CP_COMMIT() asm volatile("cp.async.commit_group;" ::: "memory")
#define CP_WAIT(N)  asm volatile("cp.async.wait_group %0;" :: "n"(N) : "memory")

__device__ __forceinline__ void split1(float v, __nv_bfloat16& h, __nv_bfloat16& l) {
    h = __float2bfloat16(v);
    l = __float2bfloat16(v - __bfloat162float(h));
}

// ---------------- bf16-split GEMM (2-stage cp.async pipeline, 2 CTAs/SM) ----------------
__global__ __launch_bounds__(GTHREADS, 2) void gemm_bf16s(
    const __nv_bfloat16* __restrict__ AH, const __nv_bfloat16* __restrict__ AL,
    const __nv_bfloat16* __restrict__ BH, const __nv_bfloat16* __restrict__ BL,
    const float* __restrict__ bias, const float* __restrict__ bias2, const float* __restrict__ bias3,
    const float* __restrict__ resid,
    float* __restrict__ C, __nv_bfloat16* __restrict__ OH, __nv_bfloat16* __restrict__ OL,
    int K, int lda, int ldb, int ldc,
    long sAb, long sAh, long sBb, long sBh, long sCb, long sCh, int nh,
    float alpha, int mode)
{
    extern __shared__ char smem[];
    const uint32_t sbase = smem_u32(smem);
    const int tid = threadIdx.x;
    const int wid = tid >> 5;
    const int lane = tid & 31;

    int z = blockIdx.z;
    int bz = z / nh, hz = z % nh;
    const long aoff = (long)bz * sAb + (long)hz * sAh;
    const long boff = (long)bz * sBb + (long)hz * sBh;
    const long coff = (long)bz * sCb + (long)hz * sCh;
    AH += aoff; AL += aoff;
    BH += boff; BL += boff;

    const float* bb = bias;
    if (bias2) bb = (hz == 0) ? bias : ((hz == 1) ? bias2 : bias3);

    const int bm = blockIdx.y * GBM;
    const int bn = blockIdx.x * GBN;

    const int wm = wid >> 2;
    const int wn = wid & 3;

    const uint32_t aOff = (uint32_t)(wm * 64 + (lane & 15)) * PITCH + (lane >> 4) * 16;
    const uint32_t bOff = 2 * HALF_SZ
        + (uint32_t)(wn * 32 + ((lane >> 4) << 3) + (lane & 7)) * PITCH + ((lane >> 3) & 1) * 16;

    const int cid0 = tid * 2, cid1 = cid0 + 1;
    const int r0 = cid0 >> 2, c0 = cid0 & 3;
    const int r1 = cid1 >> 2, c1 = cid1 & 3;
    const __nv_bfloat16* aH0 = AH + (long)(bm + r0) * lda + c0 * 8;
    const __nv_bfloat16* aH1 = AH + (long)(bm + r1) * lda + c1 * 8;
    const __nv_bfloat16* aL0 = AL + (long)(bm + r0) * lda + c0 * 8;
    const __nv_bfloat16* aL1 = AL + (long)(bm + r1) * lda + c1 * 8;
    const __nv_bfloat16* bH0 = BH + (long)(bn + r0) * ldb + c0 * 8;
    const __nv_bfloat16* bH1 = BH + (long)(bn + r1) * ldb + c1 * 8;
    const __nv_bfloat16* bL0 = BL + (long)(bn + r0) * ldb + c0 * 8;
    const __nv_bfloat16* bL1 = BL + (long)(bn + r1) * ldb + c1 * 8;
    const uint32_t d0 = (uint32_t)(r0 * PITCH + c0 * 16);
    const uint32_t d1 = (uint32_t)(r1 * PITCH + c1 * 16);

#define ISSUE_STAGE(SIDX, KO) do {                                   \
        uint32_t s_ = sbase + (uint32_t)(SIDX) * STG;                \
        long ko_ = (KO);                                             \
        cpasync16(s_ + d0,             aH0 + ko_);                   \
        cpasync16(s_ + d1,             aH1 + ko_);                   \
        cpasync16(s_ + HALF_SZ + d0,   aL0 + ko_);                   \
        cpasync16(s_ + HALF_SZ + d1,   aL1 + ko_);                   \
        cpasync16(s_ + 2*HALF_SZ + d0, bH0 + ko_);                   \
        cpasync16(s_ + 2*HALF_SZ + d1, bH1 + ko_);                   \
        cpasync16(s_ + 3*HALF_SZ + d0, bL0 + ko_);                   \
        cpasync16(s_ + 3*HALF_SZ + d1, bL1 + ko_);                   \
    } while (0)

    float acc[4][4][4];
    #pragma unroll
    for (int i = 0; i < 4; i++)
        #pragma unroll
        for (int j = 0; j < 4; j++)
            #pragma unroll
            for (int r = 0; r < 4; r++) acc[i][j][r] = 0.f;

    const int NKI = K / GBK;

    // prologue: issue stage 0
    ISSUE_STAGE(0, 0L);
    CP_COMMIT();

    for (int i = 0; i < NKI; i++) {
        CP_WAIT(0);          // stage i arrived (issued one iteration earlier)
        __syncthreads();     // all warps done computing stage i-1 -> other buffer free

        if (i + 1 < NKI) ISSUE_STAGE((i + 1) & (NSTAGE - 1), (long)(i + 1) * GBK);
        CP_COMMIT();

        const uint32_t sb = sbase + (uint32_t)(i & (NSTAGE - 1)) * STG;
        #pragma unroll
        for (int ks = 0; ks < 2; ks++) {
            uint32_t afh[4][4], afl[4][4];
            uint32_t bfh[2][4], bfl[2][4];
            #pragma unroll
            for (int mf = 0; mf < 4; mf++) {
                uint32_t ad = sb + aOff + mf * (16 * PITCH) + ks * 32;
                ldsm4(afh[mf], ad);
                ldsm4(afl[mf], ad + HALF_SZ);
            }
            #pragma unroll
            for (int np = 0; np < 2; np++) {
                uint32_t bd = sb + bOff + np * (16 * PITCH) + ks * 32;
                ldsm4(bfh[np], bd);
                ldsm4(bfl[np], bd + HALF_SZ);
            }
            #pragma unroll
            for (int mf = 0; mf < 4; mf++) {
                #pragma unroll
                for (int nf = 0; nf < 4; nf++) {
                    const int np = nf >> 1;
                    const int pr = (nf & 1) * 2;
                    mma_bf16(acc[mf][nf], afh[mf], &bfh[np][pr]);
                    mma_bf16(acc[mf][nf], afh[mf], &bfl[np][pr]);
                    mma_bf16(acc[mf][nf], afl[mf], &bfh[np][pr]);
                }
            }
        }
        __syncthreads();     // reads of stage i done before next iter's cp.async overwrite
    }
#undef ISSUE_STAGE

    float* Cp = C ? C + coff : nullptr;
    __nv_bfloat16* OHp = OH ? OH + coff : nullptr;
    __nv_bfloat16* OLp = OL ? OL + coff : nullptr;
    const int g = lane >> 2;
    const int t = lane & 3;
    #pragma unroll
    for (int mf = 0; mf < 4; mf++) {
        #pragma unroll
        for (int nf = 0; nf < 4; nf++) {
            int row0 = bm + wm * 64 + mf * 16 + g;
            int col = bn + wn * 32 + nf * 8 + t * 2;
            float2 v0, v1;
            v0.x = acc[mf][nf][0] * alpha;
            v0.y = acc[mf][nf][1] * alpha;
            v1.x = acc[mf][nf][2] * alpha;
            v1.y = acc[mf][nf][3] * alpha;
            if (bb) {
                float2 bbv = *(const float2*)(bb + col);
                v0.x += bbv.x; v0.y += bbv.y;
                v1.x += bbv.x; v1.y += bbv.y;
            }
            long o0 = (long)row0 * ldc + col;
            long o1 = (long)(row0 + 8) * ldc + col;
            if (mode & EPI_SWIGLU) {
                float2 rr0 = *(const float2*)(resid + o0);
                float2 rr1 = *(const float2*)(resid + o1);
                v0.x = rr0.x * (1.0f / (1.0f + expf(-rr0.x))) * v0.x;
                v0.y = rr0.y * (1.0f / (1.0f + expf(-rr0.y))) * v0.y;
                v1.x = rr1.x * (1.0f / (1.0f + expf(-rr1.x))) * v1.x;
                v1.y = rr1.y * (1.0f / (1.0f + expf(-rr1.y))) * v1.y;
            }
            if (mode & EPI_SPLIT) {
                __nv_bfloat162 h0, l0, h1, l1;
                split1(v0.x, h0.x, l0.x); split1(v0.y, h0.y, l0.y);
                split1(v1.x, h1.x, l1.x); split1(v1.y, h1.y, l1.y);
                *(__nv_bfloat162*)(OHp + o0) = h0;
                *(__nv_bfloat162*)(OLp + o0) = l0;
                *(__nv_bfloat162*)(OHp + o1) = h1;
                *(__nv_bfloat162*)(OLp + o1) = l1;
            }
            if (mode & EPI_C) {
                if (resid) {
                    float2 rr0 = *(const float2*)(resid + o0);
                    float2 rr1 = *(const float2*)(resid + o1);
                    v0.x += rr0.x; v0.y += rr0.y;
                    v1.x += rr1.x; v1.y += rr1.y;
                }
                *(float2*)(Cp + o0) = v0;
                *(float2*)(Cp + o1) = v1;
            }
        }
    }
}

// ---------------- merged weight transpose + split: z selects one of 7 weights ----------------
__global__ __launch_bounds__(256) void transpose_split_w7(
    const float* __restrict__ w0, const float* __restrict__ w1,
    const float* __restrict__ w2, const float* __restrict__ w3,
    const float* __restrict__ w4, const float* __restrict__ w5,
    const float* __restrict__ w6,
    __nv_bfloat16* __restrict__ oH, __nv_bfloat16* __restrict__ oL)
{
    __shared__ float tile[32][33];
    const int z = blockIdx.z;
    const float* in;
    switch (z) {
        case 0: in = w0; break;
        case 1: in = w1; break;
        case 2: in = w2; break;
        case 3: in = w3; break;
        case 4: in = w4; break;
        case 5: in = w5; break;
        default: in = w6; break;
    }
    long ob = (long)z * DD * DD;
    oH += ob; oL += ob;
    int c0 = blockIdx.x << 5, r0 = blockIdx.y << 5;
    int tx = threadIdx.x & 31, ty = threadIdx.x >> 5;
    #pragma unroll
    for (int j = 0; j < 4; j++)
        tile[ty + j * 8][tx] = in[(long)(r0 + ty + j * 8) * DD + c0 + tx];
    __syncthreads();
    #pragma unroll
    for (int j = 0; j < 4; j++) {
        float val = tile[tx][ty + j * 8];
        __nv_bfloat16 h, l;
        split1(val, h, l);
        long o = (long)(c0 + ty + j * 8) * DD + r0 + tx;
        oH[o] = h; oL[o] = l;
    }
}

// ---------------- transpose + split (bf16 hi/lo input) ----------------
__global__ __launch_bounds__(256) void transpose_split_bf2(
    const __nv_bfloat16* __restrict__ inH, const __nv_bfloat16* __restrict__ inL,
    __nv_bfloat16* __restrict__ oH, __nv_bfloat16* __restrict__ oL,
    int ldin, int ldout, long sInB, long sInH, long sOutB, long sOutH, int nh)
{
    __shared__ float tile[32][33];
    int z = blockIdx.z, bz = z / nh, hz = z % nh;
    long ib = (long)bz * sInB + (long)hz * sInH;
    inH += ib; inL += ib;
    long ob = (long)bz * sOutB + (long)hz * sOutH;
    oH += ob; oL += ob;
    int c0 = blockIdx.x << 5, r0 = blockIdx.y << 5;
    int tx = threadIdx.x & 31, ty = threadIdx.x >> 5;
    #pragma unroll
    for (int j = 0; j < 4; j++) {
        long idx = (long)(r0 + ty + j * 8) * ldin + c0 + tx;
        tile[ty + j * 8][tx] = __bfloat162float(inH[idx]) + __bfloat162float(inL[idx]);
    }
    __syncthreads();
    #pragma unroll
    for (int j = 0; j < 4; j++) {
        float val = tile[tx][ty + j * 8];
        __nv_bfloat16 h, l;
        split1(val, h, l);
        long o = (long)(c0 + ty + j * 8) * ldout + r0 + tx;
        oH[o] = h; oL[o] = l;
    }
}

// ---------------- block reductions ----------------
__device__ __forceinline__ float block_reduce_sum(float v) {
    __shared__ float sh[8];
    #pragma unroll
    for (int o = 16; o > 0; o >>= 1) v += __shfl_xor_sync(0xffffffffu, v, o);
    int w = threadIdx.x >> 5;
    if ((threadIdx.x & 31) == 0) sh[w] = v;
    __syncthreads();
    if (threadIdx.x < 8) {
        v = sh[threadIdx.x];
        #pragma unroll
        for (int o = 4; o > 0; o >>= 1) v += __shfl_xor_sync(0xffu, v, o);
        if (threadIdx.x == 0) sh[0] = v;
    }
    __syncthreads();
    float r = sh[0];
    __syncthreads();
    return r;
}
__device__ __forceinline__ float block_reduce_max(float v) {
    __shared__ float sh[8];
    #pragma unroll
    for (int o = 16; o > 0; o >>= 1) v = fmaxf(v, __shfl_xor_sync(0xffffffffu, v, o));
    int w = threadIdx.x >> 5;
    if ((threadIdx.x & 31) == 0) sh[w] = v;
    __syncthreads();
    if (threadIdx.x < 8) {
        v = sh[threadIdx.x];
        #pragma unroll
        for (int o = 4; o > 0; o >>= 1) v = fmaxf(v, __shfl_xor_sync(0xffu, v, o));
        if (threadIdx.x == 0) sh[0] = v;
    }
    __syncthreads();
    float r = sh[0];
    __syncthreads();
    return r;
}

// ---------------- RMSNorm -> split bf16 ----------------
__global__ __launch_bounds__(256) void rmsnorm_split(
    const float* __restrict__ x, const float* __restrict__ scale,
    __nv_bfloat16* __restrict__ yH, __nv_bfloat16* __restrict__ yL)
{
    long row = blockIdx.x;
    const float* xr = x + row * (long)DD;
    float vals[8];
    float ss = 0.f;
    #pragma unroll
    for (int i = 0; i < 8; i++) {
        int idx = threadIdx.x + i * 256;
        float v = xr[idx];
        vals[i] = v;
        ss += v * v;
    }
    ss = block_reduce_sum(ss);
    float r = rsqrtf(ss * (1.0f / DD) + 1e-5f);
    long base = row * (long)DD;
    #pragma unroll
    for (int i = 0; i < 8; i++) {
        int idx = threadIdx.x + i * 256;
        float v = scale[idx] * vals[i] * r;
        __nv_bfloat16 h, l;
        split1(v, h, l);
        yH[base + idx] = h; yL[base + idx] = l;
    }
}

// ---------------- softmax -> split bf16 probs (vectorized) ----------------
__global__ __launch_bounds__(256) void softmax_split(
    const float* __restrict__ e,
    __nv_bfloat16* __restrict__ pH, __nv_bfloat16* __restrict__ pL)
{
    long base = (long)blockIdx.x * TT;
    const float4* p4 = (const float4*)(e + base);
    float4 vals[2];
    float m = -1e30f;
    #pragma unroll
    for (int i = 0; i < 2; i++) {
        vals[i] = p4[threadIdx.x + i * 256];
        m = fmaxf(m, fmaxf(fmaxf(vals[i].x, vals[i].y), fmaxf(vals[i].z, vals[i].w)));
    }
    m = block_reduce_max(m);
    float s = 0.f;
    #pragma unroll
    for (int i = 0; i < 2; i++) {
        vals[i].x = expf(vals[i].x - m);
        vals[i].y = expf(vals[i].y - m);
        vals[i].z = expf(vals[i].z - m);
        vals[i].w = expf(vals[i].w - m);
        s += vals[i].x + vals[i].y + vals[i].z + vals[i].w;
    }
    s = block_reduce_sum(s);
    float inv = 1.0f / s;
    #pragma unroll
    for (int i = 0; i < 2; i++) {
        long o = base + (threadIdx.x + i * 256) * 4;
        __nv_bfloat162 h0, l0, h1, l1;
        split1(vals[i].x * inv, h0.x, l0.x);
        split1(vals[i].y * inv, h0.y, l0.y);
        split1(vals[i].z * inv, h1.x, l1.x);
        split1(vals[i].w * inv, h1.y, l1.y);
        *(__nv_bfloat162*)(pH + o) = h0;
        *(__nv_bfloat162*)(pH + o + 2) = h1;
        *(__nv_bfloat162*)(pL + o) = l0;
        *(__nv_bfloat162*)(pL + o + 2) = l1;
    }
}

// ---------------- launcher ----------------
extern "C" void kernel_launch(void* const* d_in, const int* in_sizes, int n_in,
                              void* d_out, int out_size) {
    const float* x      = (const float*)d_in[0];
    const float* Wq     = (const float*)d_in[1];
    const float* bq     = (const float*)d_in[2];
    const float* Wk     = (const float*)d_in[3];
    const float* bk     = (const float*)d_in[4];
    const float* Wv     = (const float*)d_in[5];
    const float* bv     = (const float*)d_in[6];
    const float* Wo     = (const float*)d_in[7];
    const float* bo     = (const float*)d_in[8];
    const float* scale1 = (const float*)d_in[9];
    const float* scale2 = (const float*)d_in[10];
    const float* W1     = (const float*)d_in[11];
    const float* W2     = (const float*)d_in[12];
    const float* W3     = (const float*)d_in[13];
    float* out = (float*)d_out;

    __nv_bfloat16 *nH, *nL, *qkvH, *qkvL, *vTH, *vTL, *ctxH, *ctxL;
    __nv_bfloat16 *x1H, *x1L, *gH, *gL, *wH, *wL, *pH, *pL;
    float *h2, *x1, *energy;
    cudaGetSymbolAddress((void**)&nH, g_nH);     cudaGetSymbolAddress((void**)&nL, g_nL);
    cudaGetSymbolAddress((void**)&qkvH, g_qkvH); cudaGetSymbolAddress((void**)&qkvL, g_qkvL);
    cudaGetSymbolAddress((void**)&vTH, g_vTH);   cudaGetSymbolAddress((void**)&vTL, g_vTL);
    cudaGetSymbolAddress((void**)&ctxH, g_ctxH); cudaGetSymbolAddress((void**)&ctxL, g_ctxL);
    cudaGetSymbolAddress((void**)&h2, g_h2);
    cudaGetSymbolAddress((void**)&x1, g_x1);
    cudaGetSymbolAddress((void**)&x1H, g_x1H);   cudaGetSymbolAddress((void**)&x1L, g_x1L);
    cudaGetSymbolAddress((void**)&gH, g_gH);     cudaGetSymbolAddress((void**)&gL, g_gL);
    cudaGetSymbolAddress((void**)&wH, g_wH);     cudaGetSymbolAddress((void**)&wL, g_wL);
    cudaGetSymbolAddress((void**)&pH, g_pH);     cudaGetSymbolAddress((void**)&pL, g_pL);
    cudaGetSymbolAddress((void**)&energy, g_energy);

    cudaFuncSetAttribute(gemm_bf16s, cudaFuncAttributeMaxDynamicSharedMemorySize, GEMM_SMEM);

    const float inv_sqrt_hd = 0.08838834764831845f;
    const long DSQ = (long)DD * DD;
    __nv_bfloat16 *WoH = wH + 3*DSQ, *WoL = wL + 3*DSQ;
    __nv_bfloat16 *W1H = wH + 4*DSQ, *W1L = wL + 4*DSQ;
    __nv_bfloat16 *W2H = wH + 5*DSQ, *W2L = wL + 5*DSQ;
    __nv_bfloat16 *W3H = wH + 6*DSQ, *W3L = wL + 6*DSQ;

    // 0. ALL 7 weight transposes in ONE launch (z = weight index; slice order q,k,v,o,1,2,3)
    dim3 tgridW7(DD / 32, DD / 32, 7);
    transpose_split_w7<<<tgridW7, 256>>>(Wq, Wk, Wv, Wo, W1, W2, W3, wH, wL);

    dim3 gridDense(DD / GBN, MM / GBM, 1);
    dim3 gridQKV(DD / GBN, MM / GBM, 3);
    dim3 gridQK(TT / GBN, TT / GBM, BB * NHH);
    dim3 gridPV(1, TT / GBM, BB * NHH);

    // 1. norm1
    rmsnorm_split<<<MM, 256>>>(x, scale1, nH, nL);

    // 2. Q/K/V projections in ONE launch (z selects weight slice / bias / output slice)
    gemm_bf16s<<<gridQKV, GTHREADS, GEMM_SMEM>>>(nH, nL, wH, wL, bq, bk, bv, nullptr,
        nullptr, qkvH, qkvL, DD, DD, DD, DD,
        0, 0, 0, DSQ, 0, ELEMS, 3, 1.0f, EPI_SPLIT);

    // 3. vT split: [b,h][d][t] from V slice (z=2)
    dim3 tgridV(HDD / 32, TT / 32, BB * NHH);
    transpose_split_bf2<<<tgridV, 256>>>(qkvH + 2*ELEMS, qkvL + 2*ELEMS, vTH, vTL,
        DD, TT,
        (long)TT * DD, (long)HDD,
        (long)NHH * HDD * TT, (long)HDD * TT, NHH);

    // 4. energy = Q K^T / sqrt(HD)  (fp32)
    gemm_bf16s<<<gridQK, GTHREADS, GEMM_SMEM>>>(qkvH, qkvL, qkvH + ELEMS, qkvL + ELEMS,
        nullptr, nullptr, nullptr, nullptr,
        energy, nullptr, nullptr,
        HDD, DD, DD, TT,
        (long)TT * DD, (long)HDD,
        (long)TT * DD, (long)HDD,
        (long)NHH * TT * TT, (long)TT * TT,
        NHH, inv_sqrt_hd, EPI_C);

    // 5. softmax -> split probs
    softmax_split<<<BB * NHH * TT, 256>>>(energy, pH, pL);

    // 6. ctx = P @ V
    gemm_bf16s<<<gridPV, GTHREADS, GEMM_SMEM>>>(pH, pL, vTH, vTL,
        nullptr, nullptr, nullptr, nullptr,
        nullptr, ctxH, ctxL,
        TT, TT, TT, DD,
        (long)NHH * TT * TT, (long)TT * TT,
        (long)NHH * HDD * TT, (long)HDD * TT,
        (long)TT * DD, (long)HDD,
        NHH, 1.0f, EPI_SPLIT);

    // 7. h2 = ctx @ Wo + bo + x
    gemm_bf16s<<<gridDense, GTHREADS, GEMM_SMEM>>>(ctxH, ctxL, WoH, WoL, bo, nullptr, nullptr, x,
        h2, nullptr, nullptr, DD, DD, DD, DD, 0,0,0,0,0,0, 1, 1.0f, EPI_C);

    // 8. norm2
    rmsnorm_split<<<MM, 256>>>(h2, scale2, nH, nL);

    // 9. x1 = norm @ W1 (fp32 + split)
    gemm_bf16s<<<gridDense, GTHREADS, GEMM_SMEM>>>(nH, nL, W1H, W1L, nullptr, nullptr, nullptr, nullptr,
        x1, x1H, x1L, DD, DD, DD, DD, 0,0,0,0,0,0, 1, 1.0f, EPI_C | EPI_SPLIT);

    // 10+11. x2 = x1 @ W2 with fused swiglu: g = x1*sigmoid(x1)*x2 -> split
    gemm_bf16s<<<gridDense, GTHREADS, GEMM_SMEM>>>(x1H, x1L, W2H, W2L, nullptr, nullptr, nullptr, x1,
        nullptr, gH, gL, DD, DD, DD, DD, 0,0,0,0,0,0, 1, 1.0f, EPI_SWIGLU | EPI_SPLIT);

    // 12. out = g @ W3 + x
    gemm_bf16s<<<gridDense, GTHREADS, GEMM_SMEM>>>(gH, gL, W3H, W3L, nullptr, nullptr, nullptr, x,
        out, nullptr, nullptr, DD, DD, DD, DD, 0,0,0,0,0,0, 1, 1.0f, EPI_C);
}

// round 15
// speedup vs baseline: 1.0215x; 1.0062x over previous
#include <cuda_runtime.h>
#include <cuda_bf16.h>
#include <cstdint>
#include <math.h>

// ---------------- problem constants ----------------
#define BB  2
#define TT  2048
#define DD  2048
#define NHH 16
#define HDD 128
#define MM  (BB*TT)
#define ELEMS ((long)BB*TT*DD)
#define ESZ ((long)BB*NHH*TT*TT)

// GEMM tiling
#define GBM 128
#define GBN 128
#define GBK 32
#define GTHREADS 256

// SMEM: per stage 4 halves (AH, AL, BH, BL), 128 rows x 80B pitch each
#define PITCH 80
#define HALF_SZ 10240
#define STG 40960
#define NSTAGE 2
#define GEMM_SMEM (NSTAGE*STG)   // 81920 bytes -> 2 CTAs/SM

// epilogue modes (bitmask)
#define EPI_C      1   // write fp32 C (+resid)
#define EPI_SPLIT  2   // write split bf16 OH/OL of val
#define EPI_SWIGLU 4   // val = resid*sigmoid(resid)*val, then split write

// ---------------- scratch (static device memory) ----------------
__device__ __nv_bfloat16 g_nH[ELEMS], g_nL[ELEMS];
__device__ __nv_bfloat16 g_qkvH[3*ELEMS], g_qkvL[3*ELEMS];
__device__ __nv_bfloat16 g_vTH[ELEMS], g_vTL[ELEMS];
__device__ __nv_bfloat16 g_ctxH[ELEMS], g_ctxL[ELEMS];
__device__ float g_h2[ELEMS];
__device__ float g_x1[ELEMS];
__device__ __nv_bfloat16 g_x1H[ELEMS], g_x1L[ELEMS];
__device__ __nv_bfloat16 g_gH[ELEMS], g_gL[ELEMS];
__device__ __nv_bfloat16 g_wH[7L*DD*DD], g_wL[7L*DD*DD];
__device__ float g_energy[ESZ];
__device__ __nv_bfloat16 g_pH[ESZ], g_pL[ESZ];

// ---------------- helpers ----------------
__device__ __forceinline__ uint32_t smem_u32(const void* p) {
    uint32_t a;
    asm("{ .reg .u64 t; cvta.to.shared.u64 t, %1; cvt.u32.u64 %0, t; }" : "=r"(a) : "l"(p));
    return a;
}
__device__ __forceinline__ void ldsm4(uint32_t* r, uint32_t addr) {
    asm volatile("ldmatrix.sync.aligned.m8n8.x4.shared.b16 {%0,%1,%2,%3}, [%4];"
        : "=r"(r[0]), "=r"(r[1]), "=r"(r[2]), "=r"(r[3]) : "r"(addr));
}
__device__ __forceinline__ void mma_bf16(float* c, const uint32_t* a, const uint32_t* b) {
    asm volatile(
        "mma.sync.aligned.m16n8k16.row.col.f32.bf16.bf16.f32 "
        "{%0,%1,%2,%3}, {%4,%5,%6,%7}, {%8,%9}, {%0,%1,%2,%3};"
        : "+f"(c[0]), "+f"(c[1]), "+f"(c[2]), "+f"(c[3])
        : "r"(a[0]), "r"(a[1]), "r"(a[2]), "r"(a[3]), "r"(b[0]), "r"(b[1]));
}
__device__ __forceinline__ void cpasync16(uint32_t dst, const void* src) {
    asm volatile("cp.async.cg.shared.global [%0], [%1], 16;" :: "r"(dst), "l"(src));
}
#define CP_COMMIT() asm volatile("cp.async.commit_group;" ::: "memory")
#define CP_WAIT(N)  asm volatile("cp.async.wait_group %0;" :: "n"(N) : "memory")

__device__ __forceinline__ void split1(float v, __nv_bfloat16& h, __nv_bfloat16& l) {
    h = __float2bfloat16(v);
    l = __float2bfloat16(v - __bfloat162float(h));
}

// ---------------- bf16-split GEMM (2-stage cp.async pipeline, 2 CTAs/SM, 1 sync/iter) ----------------
__global__ __launch_bounds__(GTHREADS, 2) void gemm_bf16s(
    const __nv_bfloat16* __restrict__ AH, const __nv_bfloat16* __restrict__ AL,
    const __nv_bfloat16* __restrict__ BH, const __nv_bfloat16* __restrict__ BL,
    const float* __restrict__ bias, const float* __restrict__ bias2, const float* __restrict__ bias3,
    const float* __restrict__ resid,
    float* __restrict__ C, __nv_bfloat16* __restrict__ OH, __nv_bfloat16* __restrict__ OL,
    int K, int lda, int ldb, int ldc,
    long sAb, long sAh, long sBb, long sBh, long sCb, long sCh, int nh,
    float alpha, int mode)
{
    extern __shared__ char smem[];
    const uint32_t sbase = smem_u32(smem);
    const int tid = threadIdx.x;
    const int wid = tid >> 5;
    const int lane = tid & 31;

    int z = blockIdx.z;
    int bz = z / nh, hz = z % nh;
    const long aoff = (long)bz * sAb + (long)hz * sAh;
    const long boff = (long)bz * sBb + (long)hz * sBh;
    const long coff = (long)bz * sCb + (long)hz * sCh;
    AH += aoff; AL += aoff;
    BH += boff; BL += boff;

    const float* bb = bias;
    if (bias2) bb = (hz == 0) ? bias : ((hz == 1) ? bias2 : bias3);

    const int bm = blockIdx.y * GBM;
    const int bn = blockIdx.x * GBN;

    const int wm = wid >> 2;
    const int wn = wid & 3;

    const uint32_t aOff = (uint32_t)(wm * 64 + (lane & 15)) * PITCH + (lane >> 4) * 16;
    const uint32_t bOff = 2 * HALF_SZ
        + (uint32_t)(wn * 32 + ((lane >> 4) << 3) + (lane & 7)) * PITCH + ((lane >> 3) & 1) * 16;

    const int cid0 = tid * 2, cid1 = cid0 + 1;
    const int r0 = cid0 >> 2, c0 = cid0 & 3;
    const int r1 = cid1 >> 2, c1 = cid1 & 3;
    const __nv_bfloat16* aH0 = AH + (long)(bm + r0) * lda + c0 * 8;
    const __nv_bfloat16* aH1 = AH + (long)(bm + r1) * lda + c1 * 8;
    const __nv_bfloat16* aL0 = AL + (long)(bm + r0) * lda + c0 * 8;
    const __nv_bfloat16* aL1 = AL + (long)(bm + r1) * lda + c1 * 8;
    const __nv_bfloat16* bH0 = BH + (long)(bn + r0) * ldb + c0 * 8;
    const __nv_bfloat16* bH1 = BH + (long)(bn + r1) * ldb + c1 * 8;
    const __nv_bfloat16* bL0 = BL + (long)(bn + r0) * ldb + c0 * 8;
    const __nv_bfloat16* bL1 = BL + (long)(bn + r1) * ldb + c1 * 8;
    const uint32_t d0 = (uint32_t)(r0 * PITCH + c0 * 16);
    const uint32_t d1 = (uint32_t)(r1 * PITCH + c1 * 16);

#define ISSUE_STAGE(SIDX, KO) do {                                   \
        uint32_t s_ = sbase + (uint32_t)(SIDX) * STG;                \
        long ko_ = (KO);                                             \
        cpasync16(s_ + d0,             aH0 + ko_);                   \
        cpasync16(s_ + d1,             aH1 + ko_);                   \
        cpasync16(s_ + HALF_SZ + d0,   aL0 + ko_);                   \
        cpasync16(s_ + HALF_SZ + d1,   aL1 + ko_);                   \
        cpasync16(s_ + 2*HALF_SZ + d0, bH0 + ko_);                   \
        cpasync16(s_ + 2*HALF_SZ + d1, bH1 + ko_);                   \
        cpasync16(s_ + 3*HALF_SZ + d0, bL0 + ko_);                   \
        cpasync16(s_ + 3*HALF_SZ + d1, bL1 + ko_);                   \
    } while (0)

    float acc[4][4][4];
    #pragma unroll
    for (int i = 0; i < 4; i++)
        #pragma unroll
        for (int j = 0; j < 4; j++)
            #pragma unroll
            for (int r = 0; r < 4; r++) acc[i][j][r] = 0.f;

    const int NKI = K / GBK;

    // prologue: issue stage 0
    ISSUE_STAGE(0, 0L);
    CP_COMMIT();

    for (int i = 0; i < NKI; i++) {
        CP_WAIT(0);          // stage i arrived (issued one iteration earlier)
        // Single barrier per iter: a thread reaches this sync only after finishing
        // its iter-(i-1) compute, so the barrier globally orders "all warps done
        // computing buffer (i+1)%2" before any thread's cp.async below overwrites it.
        __syncthreads();

        if (i + 1 < NKI) ISSUE_STAGE((i + 1) & (NSTAGE - 1), (long)(i + 1) * GBK);
        CP_COMMIT();

        const uint32_t sb = sbase + (uint32_t)(i & (NSTAGE - 1)) * STG;
        #pragma unroll
        for (int ks = 0; ks < 2; ks++) {
            uint32_t afh[4][4], afl[4][4];
            uint32_t bfh[2][4], bfl[2][4];
            #pragma unroll
            for (int mf = 0; mf < 4; mf++) {
                uint32_t ad = sb + aOff + mf * (16 * PITCH) + ks * 32;
                ldsm4(afh[mf], ad);
                ldsm4(afl[mf], ad + HALF_SZ);
            }
            #pragma unroll
            for (int np = 0; np < 2; np++) {
                uint32_t bd = sb + bOff + np * (16 * PITCH) + ks * 32;
                ldsm4(bfh[np], bd);
                ldsm4(bfl[np], bd + HALF_SZ);
            }
            #pragma unroll
            for (int mf = 0; mf < 4; mf++) {
                #pragma unroll
                for (int nf = 0; nf < 4; nf++) {
                    const int np = nf >> 1;
                    const int pr = (nf & 1) * 2;
                    mma_bf16(acc[mf][nf], afh[mf], &bfh[np][pr]);
                    mma_bf16(acc[mf][nf], afh[mf], &bfl[np][pr]);
                    mma_bf16(acc[mf][nf], afl[mf], &bfh[np][pr]);
                }
            }
        }
    }
#undef ISSUE_STAGE

    float* Cp = C ? C + coff : nullptr;
    __nv_bfloat16* OHp = OH ? OH + coff : nullptr;
    __nv_bfloat16* OLp = OL ? OL + coff : nullptr;
    const int g = lane >> 2;
    const int t = lane & 3;
    #pragma unroll
    for (int mf = 0; mf < 4; mf++) {
        #pragma unroll
        for (int nf = 0; nf < 4; nf++) {
            int row0 = bm + wm * 64 + mf * 16 + g;
            int col = bn + wn * 32 + nf * 8 + t * 2;
            float2 v0, v1;
            v0.x = acc[mf][nf][0] * alpha;
            v0.y = acc[mf][nf][1] * alpha;
            v1.x = acc[mf][nf][2] * alpha;
            v1.y = acc[mf][nf][3] * alpha;
            if (bb) {
                float2 bbv = *(const float2*)(bb + col);
                v0.x += bbv.x; v0.y += bbv.y;
                v1.x += bbv.x; v1.y += bbv.y;
            }
            long o0 = (long)row0 * ldc + col;
            long o1 = (long)(row0 + 8) * ldc + col;
            if (mode & EPI_SWIGLU) {
                float2 rr0 = *(const float2*)(resid + o0);
                float2 rr1 = *(const float2*)(resid + o1);
                v0.x = rr0.x * (1.0f / (1.0f + expf(-rr0.x))) * v0.x;
                v0.y = rr0.y * (1.0f / (1.0f + expf(-rr0.y))) * v0.y;
                v1.x = rr1.x * (1.0f / (1.0f + expf(-rr1.x))) * v1.x;
                v1.y = rr1.y * (1.0f / (1.0f + expf(-rr1.y))) * v1.y;
            }
            if (mode & EPI_SPLIT) {
                __nv_bfloat162 h0, l0, h1, l1;
                split1(v0.x, h0.x, l0.x); split1(v0.y, h0.y, l0.y);
                split1(v1.x, h1.x, l1.x); split1(v1.y, h1.y, l1.y);
                *(__nv_bfloat162*)(OHp + o0) = h0;
                *(__nv_bfloat162*)(OLp + o0) = l0;
                *(__nv_bfloat162*)(OHp + o1) = h1;
                *(__nv_bfloat162*)(OLp + o1) = l1;
            }
            if (mode & EPI_C) {
                if (resid) {
                    float2 rr0 = *(const float2*)(resid + o0);
                    float2 rr1 = *(const float2*)(resid + o1);
                    v0.x += rr0.x; v0.y += rr0.y;
                    v1.x += rr1.x; v1.y += rr1.y;
                }
                *(float2*)(Cp + o0) = v0;
                *(float2*)(Cp + o1) = v1;
            }
        }
    }
}

// ---------------- merged weight transpose + split: z selects one of 7 weights ----------------
__global__ __launch_bounds__(256) void transpose_split_w7(
    const float* __restrict__ w0, const float* __restrict__ w1,
    const float* __restrict__ w2, const float* __restrict__ w3,
    const float* __restrict__ w4, const float* __restrict__ w5,
    const float* __restrict__ w6,
    __nv_bfloat16* __restrict__ oH, __nv_bfloat16* __restrict__ oL)
{
    __shared__ float tile[32][33];
    const int z = blockIdx.z;
    const float* in;
    switch (z) {
        case 0: in = w0; break;
        case 1: in = w1; break;
        case 2: in = w2; break;
        case 3: in = w3; break;
        case 4: in = w4; break;
        case 5: in = w5; break;
        default: in = w6; break;
    }
    long ob = (long)z * DD * DD;
    oH += ob; oL += ob;
    int c0 = blockIdx.x << 5, r0 = blockIdx.y << 5;
    int tx = threadIdx.x & 31, ty = threadIdx.x >> 5;
    #pragma unroll
    for (int j = 0; j < 4; j++)
        tile[ty + j * 8][tx] = in[(long)(r0 + ty + j * 8) * DD + c0 + tx];
    __syncthreads();
    #pragma unroll
    for (int j = 0; j < 4; j++) {
        float val = tile[tx][ty + j * 8];
        __nv_bfloat16 h, l;
        split1(val, h, l);
        long o = (long)(c0 + ty + j * 8) * DD + r0 + tx;
        oH[o] = h; oL[o] = l;
    }
}

// ---------------- transpose + split (bf16 hi/lo input) ----------------
__global__ __launch_bounds__(256) void transpose_split_bf2(
    const __nv_bfloat16* __restrict__ inH, const __nv_bfloat16* __restrict__ inL,
    __nv_bfloat16* __restrict__ oH, __nv_bfloat16* __restrict__ oL,
    int ldin, int ldout, long sInB, long sInH, long sOutB, long sOutH, int nh)
{
    __shared__ float tile[32][33];
    int z = blockIdx.z, bz = z / nh, hz = z % nh;
    long ib = (long)bz * sInB + (long)hz * sInH;
    inH += ib; inL += ib;
    long ob = (long)bz * sOutB + (long)hz * sOutH;
    oH += ob; oL += ob;
    int c0 = blockIdx.x << 5, r0 = blockIdx.y << 5;
    int tx = threadIdx.x & 31, ty = threadIdx.x >> 5;
    #pragma unroll
    for (int j = 0; j < 4; j++) {
        long idx = (long)(r0 + ty + j * 8) * ldin + c0 + tx;
        tile[ty + j * 8][tx] = __bfloat162float(inH[idx]) + __bfloat162float(inL[idx]);
    }
    __syncthreads();
    #pragma unroll
    for (int j = 0; j < 4; j++) {
        float val = tile[tx][ty + j * 8];
        __nv_bfloat16 h, l;
        split1(val, h, l);
        long o = (long)(c0 + ty + j * 8) * ldout + r0 + tx;
        oH[o] = h; oL[o] = l;
    }
}

// ---------------- block reductions ----------------
__device__ __forceinline__ float block_reduce_sum(float v) {
    __shared__ float sh[8];
    #pragma unroll
    for (int o = 16; o > 0; o >>= 1) v += __shfl_xor_sync(0xffffffffu, v, o);
    int w = threadIdx.x >> 5;
    if ((threadIdx.x & 31) == 0) sh[w] = v;
    __syncthreads();
    if (threadIdx.x < 8) {
        v = sh[threadIdx.x];
        #pragma unroll
        for (int o = 4; o > 0; o >>= 1) v += __shfl_xor_sync(0xffu, v, o);
        if (threadIdx.x == 0) sh[0] = v;
    }
    __syncthreads();
    float r = sh[0];
    __syncthreads();
    return r;
}

// combined online-softmax (max, sum) block reduction: one barrier round
__device__ __forceinline__ void block_reduce_ms(float& m, float& s) {
    __shared__ float shm[8], shs[8];
    #pragma unroll
    for (int o = 16; o > 0; o >>= 1) {
        float m2 = __shfl_xor_sync(0xffffffffu, m, o);
        float s2 = __shfl_xor_sync(0xffffffffu, s, o);
        float mn = fmaxf(m, m2);
        s = s * expf(m - mn) + s2 * expf(m2 - mn);
        m = mn;
    }
    int w = threadIdx.x >> 5;
    if ((threadIdx.x & 31) == 0) { shm[w] = m; shs[w] = s; }
    __syncthreads();
    if (threadIdx.x < 8) {
        m = shm[threadIdx.x];
        s = shs[threadIdx.x];
        #pragma unroll
        for (int o = 4; o > 0; o >>= 1) {
            float m2 = __shfl_xor_sync(0xffu, m, o);
            float s2 = __shfl_xor_sync(0xffu, s, o);
            float mn = fmaxf(m, m2);
            s = s * expf(m - mn) + s2 * expf(m2 - mn);
            m = mn;
        }
        if (threadIdx.x == 0) { shm[0] = m; shs[0] = s; }
    }
    __syncthreads();
    m = shm[0];
    s = shs[0];
    __syncthreads();
}

// ---------------- RMSNorm -> split bf16 ----------------
__global__ __launch_bounds__(256) void rmsnorm_split(
    const float* __restrict__ x, const float* __restrict__ scale,
    __nv_bfloat16* __restrict__ yH, __nv_bfloat16* __restrict__ yL)
{
    long row = blockIdx.x;
    const float* xr = x + row * (long)DD;
    float vals[8];
    float ss = 0.f;
    #pragma unroll
    for (int i = 0; i < 8; i++) {
        int idx = threadIdx.x + i * 256;
        float v = xr[idx];
        vals[i] = v;
        ss += v * v;
    }
    ss = block_reduce_sum(ss);
    float r = rsqrtf(ss * (1.0f / DD) + 1e-5f);
    long base = row * (long)DD;
    #pragma unroll
    for (int i = 0; i < 8; i++) {
        int idx = threadIdx.x + i * 256;
        float v = scale[idx] * vals[i] * r;
        __nv_bfloat16 h, l;
        split1(v, h, l);
        yH[base + idx] = h; yL[base + idx] = l;
    }
}

// ---------------- softmax -> split bf16 probs (single combined reduction) ----------------
__global__ __launch_bounds__(256) void softmax_split(
    const float* __restrict__ e,
    __nv_bfloat16* __restrict__ pH, __nv_bfloat16* __restrict__ pL)
{
    long base = (long)blockIdx.x * TT;
    const float4* p4 = (const float4*)(e + base);
    float4 vals[2];
    float m = -1e30f;
    #pragma unroll
    for (int i = 0; i < 2; i++) {
        vals[i] = p4[threadIdx.x + i * 256];
        m = fmaxf(m, fmaxf(fmaxf(vals[i].x, vals[i].y), fmaxf(vals[i].z, vals[i].w)));
    }
    // local sum at local max, then one combined (m, s) block reduction
    float s = 0.f;
    #pragma unroll
    for (int i = 0; i < 2; i++) {
        s += expf(vals[i].x - m) + expf(vals[i].y - m)
           + expf(vals[i].z - m) + expf(vals[i].w - m);
    }
    block_reduce_ms(m, s);
    float inv = 1.0f / s;
    #pragma unroll
    for (int i = 0; i < 2; i++) {
        long o = base + (threadIdx.x + i * 256) * 4;
        __nv_bfloat162 h0, l0, h1, l1;
        split1(expf(vals[i].x - m) * inv, h0.x, l0.x);
        split1(expf(vals[i].y - m) * inv, h0.y, l0.y);
        split1(expf(vals[i].z - m) * inv, h1.x, l1.x);
        split1(expf(vals[i].w - m) * inv, h1.y, l1.y);
        *(__nv_bfloat162*)(pH + o) = h0;
        *(__nv_bfloat162*)(pH + o + 2) = h1;
        *(__nv_bfloat162*)(pL + o) = l0;
        *(__nv_bfloat162*)(pL + o + 2) = l1;
    }
}

// ---------------- launcher ----------------
extern "C" void kernel_launch(void* const* d_in, const int* in_sizes, int n_in,
                              void* d_out, int out_size) {
    const float* x      = (const float*)d_in[0];
    const float* Wq     = (const float*)d_in[1];
    const float* bq     = (const float*)d_in[2];
    const float* Wk     = (const float*)d_in[3];
    const float* bk     = (const float*)d_in[4];
    const float* Wv     = (const float*)d_in[5];
    const float* bv     = (const float*)d_in[6];
    const float* Wo     = (const float*)d_in[7];
    const float* bo     = (const float*)d_in[8];
    const float* scale1 = (const float*)d_in[9];
    const float* scale2 = (const float*)d_in[10];
    const float* W1     = (const float*)d_in[11];
    const float* W2     = (const float*)d_in[12];
    const float* W3     = (const float*)d_in[13];
    float* out = (float*)d_out;

    __nv_bfloat16 *nH, *nL, *qkvH, *qkvL, *vTH, *vTL, *ctxH, *ctxL;
    __nv_bfloat16 *x1H, *x1L, *gH, *gL, *wH, *wL, *pH, *pL;
    float *h2, *x1, *energy;
    cudaGetSymbolAddress((void**)&nH, g_nH);     cudaGetSymbolAddress((void**)&nL, g_nL);
    cudaGetSymbolAddress((void**)&qkvH, g_qkvH); cudaGetSymbolAddress((void**)&qkvL, g_qkvL);
    cudaGetSymbolAddress((void**)&vTH, g_vTH);   cudaGetSymbolAddress((void**)&vTL, g_vTL);
    cudaGetSymbolAddress((void**)&ctxH, g_ctxH); cudaGetSymbolAddress((void**)&ctxL, g_ctxL);
    cudaGetSymbolAddress((void**)&h2, g_h2);
    cudaGetSymbolAddress((void**)&x1, g_x1);
    cudaGetSymbolAddress((void**)&x1H, g_x1H);   cudaGetSymbolAddress((void**)&x1L, g_x1L);
    cudaGetSymbolAddress((void**)&gH, g_gH);     cudaGetSymbolAddress((void**)&gL, g_gL);
    cudaGetSymbolAddress((void**)&wH, g_wH);     cudaGetSymbolAddress((void**)&wL, g_wL);
    cudaGetSymbolAddress((void**)&pH, g_pH);     cudaGetSymbolAddress((void**)&pL, g_pL);
    cudaGetSymbolAddress((void**)&energy, g_energy);

    cudaFuncSetAttribute(gemm_bf16s, cudaFuncAttributeMaxDynamicSharedMemorySize, GEMM_SMEM);

    const float inv_sqrt_hd = 0.08838834764831845f;
    const long DSQ = (long)DD * DD;
    __nv_bfloat16 *WoH = wH + 3*DSQ, *WoL = wL + 3*DSQ;
    __nv_bfloat16 *W1H = wH + 4*DSQ, *W1L = wL + 4*DSQ;
    __nv_bfloat16 *W2H = wH + 5*DSQ, *W2L = wL + 5*DSQ;
    __nv_bfloat16 *W3H = wH + 6*DSQ, *W3L = wL + 6*DSQ;

    // 0. ALL 7 weight transposes in ONE launch
    dim3 tgridW7(DD / 32, DD / 32, 7);
    transpose_split_w7<<<tgridW7, 256>>>(Wq, Wk, Wv, Wo, W1, W2, W3, wH, wL);

    dim3 gridDense(DD / GBN, MM / GBM, 1);
    dim3 gridQKV(DD / GBN, MM / GBM, 3);
    dim3 gridQK(TT / GBN, TT / GBM, BB * NHH);
    dim3 gridPV(1, TT / GBM, BB * NHH);

    // 1. norm1
    rmsnorm_split<<<MM, 256>>>(x, scale1, nH, nL);

    // 2. Q/K/V projections in ONE launch
    gemm_bf16s<<<gridQKV, GTHREADS, GEMM_SMEM>>>(nH, nL, wH, wL, bq, bk, bv, nullptr,
        nullptr, qkvH, qkvL, DD, DD, DD, DD,
        0, 0, 0, DSQ, 0, ELEMS, 3, 1.0f, EPI_SPLIT);

    // 3. vT split: [b,h][d][t] from V slice (z=2)
    dim3 tgridV(HDD / 32, TT / 32, BB * NHH);
    transpose_split_bf2<<<tgridV, 256>>>(qkvH + 2*ELEMS, qkvL + 2*ELEMS, vTH, vTL,
        DD, TT,
        (long)TT * DD, (long)HDD,
        (long)NHH * HDD * TT, (long)HDD * TT, NHH);

    // 4. energy = Q K^T / sqrt(HD)  (fp32)
    gemm_bf16s<<<gridQK, GTHREADS, GEMM_SMEM>>>(qkvH, qkvL, qkvH + ELEMS, qkvL + ELEMS,
        nullptr, nullptr, nullptr, nullptr,
        energy, nullptr, nullptr,
        HDD, DD, DD, TT,
        (long)TT * DD, (long)HDD,
        (long)TT * DD, (long)HDD,
        (long)NHH * TT * TT, (long)TT * TT,
        NHH, inv_sqrt_hd, EPI_C);

    // 5. softmax -> split probs
    softmax_split<<<BB * NHH * TT, 256>>>(energy, pH, pL);

    // 6. ctx = P @ V
    gemm_bf16s<<<gridPV, GTHREADS, GEMM_SMEM>>>(pH, pL, vTH, vTL,
        nullptr, nullptr, nullptr, nullptr,
        nullptr, ctxH, ctxL,
        TT, TT, TT, DD,
        (long)NHH * TT * TT, (long)TT * TT,
        (long)NHH * HDD * TT, (long)HDD * TT,
        (long)TT * DD, (long)HDD,
        NHH, 1.0f, EPI_SPLIT);

    // 7. h2 = ctx @ Wo + bo + x
    gemm_bf16s<<<gridDense, GTHREADS, GEMM_SMEM>>>(ctxH, ctxL, WoH, WoL, bo, nullptr, nullptr, x,
        h2, nullptr, nullptr, DD, DD, DD, DD, 0,0,0,0,0,0, 1, 1.0f, EPI_C);

    // 8. norm2
    rmsnorm_split<<<MM, 256>>>(h2, scale2, nH, nL);

    // 9. x1 = norm @ W1 (fp32 + split)
    gemm_bf16s<<<gridDense, GTHREADS, GEMM_SMEM>>>(nH, nL, W1H, W1L, nullptr, nullptr, nullptr, nullptr,
        x1, x1H, x1L, DD, DD, DD, DD, 0,0,0,0,0,0, 1, 1.0f, EPI_C | EPI_SPLIT);

    // 10+11. x2 = x1 @ W2 with fused swiglu: g = x1*sigmoid(x1)*x2 -> split
    gemm_bf16s<<<gridDense, GTHREADS, GEMM_SMEM>>>(x1H, x1L, W2H, W2L, nullptr, nullptr, nullptr, x1,
        nullptr, gH, gL, DD, DD, DD, DD, 0,0,0,0,0,0, 1, 1.0f, EPI_SWIGLU | EPI_SPLIT);

    // 12. out = g @ W3 + x
    gemm_bf16s<<<gridDense, GTHREADS, GEMM_SMEM>>>(gH, gL, W3H, W3L, nullptr, nullptr, nullptr, x,
        out, nullptr, nullptr, DD, DD, DD, DD, 0,0,0,0,0,0, 1, 1.0f, EPI_C);
}

// round 16
// speedup vs baseline: 1.0338x; 1.0120x over previous
#include <cuda_runtime.h>
#include <cuda_bf16.h>
#include <cstdint>
#include <math.h>

// ---------------- problem constants ----------------
#define BB  2
#define TT  2048
#define DD  2048
#define NHH 16
#define HDD 128
#define MM  (BB*TT)
#define ELEMS ((long)BB*TT*DD)
#define ESZ ((long)BB*NHH*TT*TT)

// GEMM tiling
#define GBM 128
#define GBN 128
#define GBK 32
#define GTHREADS 256

// SMEM: per stage 4 halves (AH, AL, BH, BL), 128 rows x 80B pitch each
#define PITCH 80
#define HALF_SZ 10240
#define STG 40960
#define NSTAGE 2
#define GEMM_SMEM (NSTAGE*STG)   // 81920 bytes -> 2 CTAs/SM

// epilogue modes (bitmask)
#define EPI_C      1   // write fp32 C (+resid fp32)
#define EPI_SPLIT  2   // write split bf16 OH/OL of val
#define EPI_SWIGLU 4   // r = RH+RL (bf16 split); val = r*sigmoid(r)*val

// ---------------- scratch (static device memory) ----------------
__device__ __nv_bfloat16 g_nH[ELEMS], g_nL[ELEMS];
__device__ __nv_bfloat16 g_qkvH[3*ELEMS], g_qkvL[3*ELEMS];
__device__ __nv_bfloat16 g_vTH[ELEMS], g_vTL[ELEMS];
__device__ __nv_bfloat16 g_ctxH[ELEMS], g_ctxL[ELEMS];
__device__ float g_h2[ELEMS];
__device__ __nv_bfloat16 g_x1H[ELEMS], g_x1L[ELEMS];
__device__ __nv_bfloat16 g_gH[ELEMS], g_gL[ELEMS];
__device__ __nv_bfloat16 g_wH[7L*DD*DD], g_wL[7L*DD*DD];
__device__ float g_energy[ESZ];
__device__ __nv_bfloat16 g_pH[ESZ], g_pL[ESZ];

// ---------------- helpers ----------------
__device__ __forceinline__ uint32_t smem_u32(const void* p) {
    uint32_t a;
    asm("{ .reg .u64 t; cvta.to.shared.u64 t, %1; cvt.u32.u64 %0, t; }" : "=r"(a) : "l"(p));
    return a;
}
__device__ __forceinline__ void ldsm4(uint32_t* r, uint32_t addr) {
    asm volatile("ldmatrix.sync.aligned.m8n8.x4.shared.b16 {%0,%1,%2,%3}, [%4];"
        : "=r"(r[0]), "=r"(r[1]), "=r"(r[2]), "=r"(r[3]) : "r"(addr));
}
__device__ __forceinline__ void mma_bf16(float* c, const uint32_t* a, const uint32_t* b) {
    asm volatile(
        "mma.sync.aligned.m16n8k16.row.col.f32.bf16.bf16.f32 "
        "{%0,%1,%2,%3}, {%4,%5,%6,%7}, {%8,%9}, {%0,%1,%2,%3};"
        : "+f"(c[0]), "+f"(c[1]), "+f"(c[2]), "+f"(c[3])
        : "r"(a[0]), "r"(a[1]), "r"(a[2]), "r"(a[3]), "r"(b[0]), "r"(b[1]));
}
__device__ __forceinline__ void cpasync16(uint32_t dst, const void* src) {
    asm volatile("cp.async.cg.shared.global [%0], [%1], 16;" :: "r"(dst), "l"(src));
}
#define CP_COMMIT() asm volatile("cp.async.commit_group;" ::: "memory")
#define CP_WAIT(N)  asm volatile("cp.async.wait_group %0;" :: "n"(N) : "memory")

__device__ __forceinline__ void split1(float v, __nv_bfloat16& h, __nv_bfloat16& l) {
    h = __float2bfloat16(v);
    l = __float2bfloat16(v - __bfloat162float(h));
}

// ---------------- bf16-split GEMM (2-stage cp.async pipeline, 2 CTAs/SM, 1 sync/iter) ----------------
__global__ __launch_bounds__(GTHREADS, 2) void gemm_bf16s(
    const __nv_bfloat16* __restrict__ AH, const __nv_bfloat16* __restrict__ AL,
    const __nv_bfloat16* __restrict__ BH, const __nv_bfloat16* __restrict__ BL,
    const float* __restrict__ bias, const float* __restrict__ bias2, const float* __restrict__ bias3,
    const float* __restrict__ resid,
    const __nv_bfloat16* __restrict__ RH, const __nv_bfloat16* __restrict__ RL,
    float* __restrict__ C, __nv_bfloat16* __restrict__ OH, __nv_bfloat16* __restrict__ OL,
    int K, int lda, int ldb, int ldc,
    long sAb, long sAh, long sBb, long sBh, long sCb, long sCh, int nh,
    float alpha, int mode)
{
    extern __shared__ char smem[];
    const uint32_t sbase = smem_u32(smem);
    const int tid = threadIdx.x;
    const int wid = tid >> 5;
    const int lane = tid & 31;

    int z = blockIdx.z;
    int bz = z / nh, hz = z % nh;
    const long aoff = (long)bz * sAb + (long)hz * sAh;
    const long boff = (long)bz * sBb + (long)hz * sBh;
    const long coff = (long)bz * sCb + (long)hz * sCh;
    AH += aoff; AL += aoff;
    BH += boff; BL += boff;

    const float* bb = bias;
    if (bias2) bb = (hz == 0) ? bias : ((hz == 1) ? bias2 : bias3);

    const int bm = blockIdx.y * GBM;
    const int bn = blockIdx.x * GBN;

    const int wm = wid >> 2;
    const int wn = wid & 3;

    const uint32_t aOff = (uint32_t)(wm * 64 + (lane & 15)) * PITCH + (lane >> 4) * 16;
    const uint32_t bOff = 2 * HALF_SZ
        + (uint32_t)(wn * 32 + ((lane >> 4) << 3) + (lane & 7)) * PITCH + ((lane >> 3) & 1) * 16;

    const int cid0 = tid * 2, cid1 = cid0 + 1;
    const int r0 = cid0 >> 2, c0 = cid0 & 3;
    const int r1 = cid1 >> 2, c1 = cid1 & 3;
    const __nv_bfloat16* aH0 = AH + (long)(bm + r0) * lda + c0 * 8;
    const __nv_bfloat16* aH1 = AH + (long)(bm + r1) * lda + c1 * 8;
    const __nv_bfloat16* aL0 = AL + (long)(bm + r0) * lda + c0 * 8;
    const __nv_bfloat16* aL1 = AL + (long)(bm + r1) * lda + c1 * 8;
    const __nv_bfloat16* bH0 = BH + (long)(bn + r0) * ldb + c0 * 8;
    const __nv_bfloat16* bH1 = BH + (long)(bn + r1) * ldb + c1 * 8;
    const __nv_bfloat16* bL0 = BL + (long)(bn + r0) * ldb + c0 * 8;
    const __nv_bfloat16* bL1 = BL + (long)(bn + r1) * ldb + c1 * 8;
    const uint32_t d0 = (uint32_t)(r0 * PITCH + c0 * 16);
    const uint32_t d1 = (uint32_t)(r1 * PITCH + c1 * 16);

#define ISSUE_STAGE(SIDX, KO) do {                                   \
        uint32_t s_ = sbase + (uint32_t)(SIDX) * STG;                \
        long ko_ = (KO);                                             \
        cpasync16(s_ + d0,             aH0 + ko_);                   \
        cpasync16(s_ + d1,             aH1 + ko_);                   \
        cpasync16(s_ + HALF_SZ + d0,   aL0 + ko_);                   \
        cpasync16(s_ + HALF_SZ + d1,   aL1 + ko_);                   \
        cpasync16(s_ + 2*HALF_SZ + d0, bH0 + ko_);                   \
        cpasync16(s_ + 2*HALF_SZ + d1, bH1 + ko_);                   \
        cpasync16(s_ + 3*HALF_SZ + d0, bL0 + ko_);                   \
        cpasync16(s_ + 3*HALF_SZ + d1, bL1 + ko_);                   \
    } while (0)

    float acc[4][4][4];
    #pragma unroll
    for (int i = 0; i < 4; i++)
        #pragma unroll
        for (int j = 0; j < 4; j++)
            #pragma unroll
            for (int r = 0; r < 4; r++) acc[i][j][r] = 0.f;

    const int NKI = K / GBK;

    // prologue: issue stage 0
    ISSUE_STAGE(0, 0L);
    CP_COMMIT();

    for (int i = 0; i < NKI; i++) {
        CP_WAIT(0);          // stage i arrived (issued one iteration earlier)
        __syncthreads();     // globally orders prior-iter compute before overwrite below

        if (i + 1 < NKI) ISSUE_STAGE((i + 1) & (NSTAGE - 1), (long)(i + 1) * GBK);
        CP_COMMIT();

        const uint32_t sb = sbase + (uint32_t)(i & (NSTAGE - 1)) * STG;
        #pragma unroll
        for (int ks = 0; ks < 2; ks++) {
            uint32_t afh[4][4], afl[4][4];
            uint32_t bfh[2][4], bfl[2][4];
            #pragma unroll
            for (int mf = 0; mf < 4; mf++) {
                uint32_t ad = sb + aOff + mf * (16 * PITCH) + ks * 32;
                ldsm4(afh[mf], ad);
                ldsm4(afl[mf], ad + HALF_SZ);
            }
            #pragma unroll
            for (int np = 0; np < 2; np++) {
                uint32_t bd = sb + bOff + np * (16 * PITCH) + ks * 32;
                ldsm4(bfh[np], bd);
                ldsm4(bfl[np], bd + HALF_SZ);
            }
            #pragma unroll
            for (int mf = 0; mf < 4; mf++) {
                #pragma unroll
                for (int nf = 0; nf < 4; nf++) {
                    const int np = nf >> 1;
                    const int pr = (nf & 1) * 2;
                    mma_bf16(acc[mf][nf], afh[mf], &bfh[np][pr]);
                    mma_bf16(acc[mf][nf], afh[mf], &bfl[np][pr]);
                    mma_bf16(acc[mf][nf], afl[mf], &bfh[np][pr]);
                }
            }
        }
    }
#undef ISSUE_STAGE

    float* Cp = C ? C + coff : nullptr;
    __nv_bfloat16* OHp = OH ? OH + coff : nullptr;
    __nv_bfloat16* OLp = OL ? OL + coff : nullptr;
    const int g = lane >> 2;
    const int t = lane & 3;
    #pragma unroll
    for (int mf = 0; mf < 4; mf++) {
        #pragma unroll
        for (int nf = 0; nf < 4; nf++) {
            int row0 = bm + wm * 64 + mf * 16 + g;
            int col = bn + wn * 32 + nf * 8 + t * 2;
            float2 v0, v1;
            v0.x = acc[mf][nf][0] * alpha;
            v0.y = acc[mf][nf][1] * alpha;
            v1.x = acc[mf][nf][2] * alpha;
            v1.y = acc[mf][nf][3] * alpha;
            if (bb) {
                float2 bbv = *(const float2*)(bb + col);
                v0.x += bbv.x; v0.y += bbv.y;
                v1.x += bbv.x; v1.y += bbv.y;
            }
            long o0 = (long)row0 * ldc + col;
            long o1 = (long)(row0 + 8) * ldc + col;
            if (mode & EPI_SWIGLU) {
                // r = RH+RL (bf16 split of x1); val = r*sigmoid(r)*val
                float2 a0 = __bfloat1622float2(*(const __nv_bfloat162*)(RH + o0));
                float2 b0 = __bfloat1622float2(*(const __nv_bfloat162*)(RL + o0));
                float2 a1 = __bfloat1622float2(*(const __nv_bfloat162*)(RH + o1));
                float2 b1 = __bfloat1622float2(*(const __nv_bfloat162*)(RL + o1));
                float rx0 = a0.x + b0.x, ry0 = a0.y + b0.y;
                float rx1 = a1.x + b1.x, ry1 = a1.y + b1.y;
                v0.x = rx0 * (1.0f / (1.0f + __expf(-rx0))) * v0.x;
                v0.y = ry0 * (1.0f / (1.0f + __expf(-ry0))) * v0.y;
                v1.x = rx1 * (1.0f / (1.0f + __expf(-rx1))) * v1.x;
                v1.y = ry1 * (1.0f / (1.0f + __expf(-ry1))) * v1.y;
            }
            if (mode & EPI_SPLIT) {
                __nv_bfloat162 h0, l0, h1, l1;
                split1(v0.x, h0.x, l0.x); split1(v0.y, h0.y, l0.y);
                split1(v1.x, h1.x, l1.x); split1(v1.y, h1.y, l1.y);
                *(__nv_bfloat162*)(OHp + o0) = h0;
                *(__nv_bfloat162*)(OLp + o0) = l0;
                *(__nv_bfloat162*)(OHp + o1) = h1;
                *(__nv_bfloat162*)(OLp + o1) = l1;
            }
            if (mode & EPI_C) {
                if (resid) {
                    float2 rr0 = *(const float2*)(resid + o0);
                    float2 rr1 = *(const float2*)(resid + o1);
                    v0.x += rr0.x; v0.y += rr0.y;
                    v1.x += rr1.x; v1.y += rr1.y;
                }
                *(float2*)(Cp + o0) = v0;
                *(float2*)(Cp + o1) = v1;
            }
        }
    }
}

// ---------------- merged weight transpose + split: z selects one of 7 weights ----------------
__global__ __launch_bounds__(256) void transpose_split_w7(
    const float* __restrict__ w0, const float* __restrict__ w1,
    const float* __restrict__ w2, const float* __restrict__ w3,
    const float* __restrict__ w4, const float* __restrict__ w5,
    const float* __restrict__ w6,
    __nv_bfloat16* __restrict__ oH, __nv_bfloat16* __restrict__ oL)
{
    __shared__ float tile[32][33];
    const int z = blockIdx.z;
    const float* in;
    switch (z) {
        case 0: in = w0; break;
        case 1: in = w1; break;
        case 2: in = w2; break;
        case 3: in = w3; break;
        case 4: in = w4; break;
        case 5: in = w5; break;
        default: in = w6; break;
    }
    long ob = (long)z * DD * DD;
    oH += ob; oL += ob;
    int c0 = blockIdx.x << 5, r0 = blockIdx.y << 5;
    int tx = threadIdx.x & 31, ty = threadIdx.x >> 5;
    #pragma unroll
    for (int j = 0; j < 4; j++)
        tile[ty + j * 8][tx] = in[(long)(r0 + ty + j * 8) * DD + c0 + tx];
    __syncthreads();
    #pragma unroll
    for (int j = 0; j < 4; j++) {
        float val = tile[tx][ty + j * 8];
        __nv_bfloat16 h, l;
        split1(val, h, l);
        long o = (long)(c0 + ty + j * 8) * DD + r0 + tx;
        oH[o] = h; oL[o] = l;
    }
}

// ---------------- transpose + split (bf16 hi/lo input) ----------------
__global__ __launch_bounds__(256) void transpose_split_bf2(
    const __nv_bfloat16* __restrict__ inH, const __nv_bfloat16* __restrict__ inL,
    __nv_bfloat16* __restrict__ oH, __nv_bfloat16* __restrict__ oL,
    int ldin, int ldout, long sInB, long sInH, long sOutB, long sOutH, int nh)
{
    __shared__ float tile[32][33];
    int z = blockIdx.z, bz = z / nh, hz = z % nh;
    long ib = (long)bz * sInB + (long)hz * sInH;
    inH += ib; inL += ib;
    long ob = (long)bz * sOutB + (long)hz * sOutH;
    oH += ob; oL += ob;
    int c0 = blockIdx.x << 5, r0 = blockIdx.y << 5;
    int tx = threadIdx.x & 31, ty = threadIdx.x >> 5;
    #pragma unroll
    for (int j = 0; j < 4; j++) {
        long idx = (long)(r0 + ty + j * 8) * ldin + c0 + tx;
        tile[ty + j * 8][tx] = __bfloat162float(inH[idx]) + __bfloat162float(inL[idx]);
    }
    __syncthreads();
    #pragma unroll
    for (int j = 0; j < 4; j++) {
        float val = tile[tx][ty + j * 8];
        __nv_bfloat16 h, l;
        split1(val, h, l);
        long o = (long)(c0 + ty + j * 8) * ldout + r0 + tx;
        oH[o] = h; oL[o] = l;
    }
}

// ---------------- block reductions ----------------
__device__ __forceinline__ float block_reduce_sum(float v) {
    __shared__ float sh[8];
    #pragma unroll
    for (int o = 16; o > 0; o >>= 1) v += __shfl_xor_sync(0xffffffffu, v, o);
    int w = threadIdx.x >> 5;
    if ((threadIdx.x & 31) == 0) sh[w] = v;
    __syncthreads();
    if (threadIdx.x < 8) {
        v = sh[threadIdx.x];
        #pragma unroll
        for (int o = 4; o > 0; o >>= 1) v += __shfl_xor_sync(0xffu, v, o);
        if (threadIdx.x == 0) sh[0] = v;
    }
    __syncthreads();
    float r = sh[0];
    __syncthreads();
    return r;
}

// combined online-softmax (max, sum) block reduction: one barrier round
__device__ __forceinline__ void block_reduce_ms(float& m, float& s) {
    __shared__ float shm[8], shs[8];
    #pragma unroll
    for (int o = 16; o > 0; o >>= 1) {
        float m2 = __shfl_xor_sync(0xffffffffu, m, o);
        float s2 = __shfl_xor_sync(0xffffffffu, s, o);
        float mn = fmaxf(m, m2);
        s = s * __expf(m - mn) + s2 * __expf(m2 - mn);
        m = mn;
    }
    int w = threadIdx.x >> 5;
    if ((threadIdx.x & 31) == 0) { shm[w] = m; shs[w] = s; }
    __syncthreads();
    if (threadIdx.x < 8) {
        m = shm[threadIdx.x];
        s = shs[threadIdx.x];
        #pragma unroll
        for (int o = 4; o > 0; o >>= 1) {
            float m2 = __shfl_xor_sync(0xffu, m, o);
            float s2 = __shfl_xor_sync(0xffu, s, o);
            float mn = fmaxf(m, m2);
            s = s * __expf(m - mn) + s2 * __expf(m2 - mn);
            m = mn;
        }
        if (threadIdx.x == 0) { shm[0] = m; shs[0] = s; }
    }
    __syncthreads();
    m = shm[0];
    s = shs[0];
    __syncthreads();
}

// ---------------- RMSNorm -> split bf16 ----------------
__global__ __launch_bounds__(256) void rmsnorm_split(
    const float* __restrict__ x, const float* __restrict__ scale,
    __nv_bfloat16* __restrict__ yH, __nv_bfloat16* __restrict__ yL)
{
    long row = blockIdx.x;
    const float* xr = x + row * (long)DD;
    float vals[8];
    float ss = 0.f;
    #pragma unroll
    for (int i = 0; i < 8; i++) {
        int idx = threadIdx.x + i * 256;
        float v = xr[idx];
        vals[i] = v;
        ss += v * v;
    }
    ss = block_reduce_sum(ss);
    float r = rsqrtf(ss * (1.0f / DD) + 1e-5f);
    long base = row * (long)DD;
    #pragma unroll
    for (int i = 0; i < 8; i++) {
        int idx = threadIdx.x + i * 256;
        float v = scale[idx] * vals[i] * r;
        __nv_bfloat16 h, l;
        split1(v, h, l);
        yH[base + idx] = h; yL[base + idx] = l;
    }
}

// ---------------- softmax -> split bf16 probs (single combined reduction, fast exp) ----------------
__global__ __launch_bounds__(256) void softmax_split(
    const float* __restrict__ e,
    __nv_bfloat16* __restrict__ pH, __nv_bfloat16* __restrict__ pL)
{
    long base = (long)blockIdx.x * TT;
    const float4* p4 = (const float4*)(e + base);
    float4 vals[2];
    float m = -1e30f;
    #pragma unroll
    for (int i = 0; i < 2; i++) {
        vals[i] = p4[threadIdx.x + i * 256];
        m = fmaxf(m, fmaxf(fmaxf(vals[i].x, vals[i].y), fmaxf(vals[i].z, vals[i].w)));
    }
    float s = 0.f;
    #pragma unroll
    for (int i = 0; i < 2; i++) {
        s += __expf(vals[i].x - m) + __expf(vals[i].y - m)
           + __expf(vals[i].z - m) + __expf(vals[i].w - m);
    }
    block_reduce_ms(m, s);
    float inv = 1.0f / s;
    #pragma unroll
    for (int i = 0; i < 2; i++) {
        long o = base + (threadIdx.x + i * 256) * 4;
        __nv_bfloat162 h0, l0, h1, l1;
        split1(__expf(vals[i].x - m) * inv, h0.x, l0.x);
        split1(__expf(vals[i].y - m) * inv, h0.y, l0.y);
        split1(__expf(vals[i].z - m) * inv, h1.x, l1.x);
        split1(__expf(vals[i].w - m) * inv, h1.y, l1.y);
        *(__nv_bfloat162*)(pH + o) = h0;
        *(__nv_bfloat162*)(pH + o + 2) = h1;
        *(__nv_bfloat162*)(pL + o) = l0;
        *(__nv_bfloat162*)(pL + o + 2) = l1;
    }
}

// ---------------- launcher ----------------
extern "C" void kernel_launch(void* const* d_in, const int* in_sizes, int n_in,
                              void* d_out, int out_size) {
    const float* x      = (const float*)d_in[0];
    const float* Wq     = (const float*)d_in[1];
    const float* bq     = (const float*)d_in[2];
    const float* Wk     = (const float*)d_in[3];
    const float* bk     = (const float*)d_in[4];
    const float* Wv     = (const float*)d_in[5];
    const float* bv     = (const float*)d_in[6];
    const float* Wo     = (const float*)d_in[7];
    const float* bo     = (const float*)d_in[8];
    const float* scale1 = (const float*)d_in[9];
    const float* scale2 = (const float*)d_in[10];
    const float* W1     = (const float*)d_in[11];
    const float* W2     = (const float*)d_in[12];
    const float* W3     = (const float*)d_in[13];
    float* out = (float*)d_out;

    __nv_bfloat16 *nH, *nL, *qkvH, *qkvL, *vTH, *vTL, *ctxH, *ctxL;
    __nv_bfloat16 *x1H, *x1L, *gH, *gL, *wH, *wL, *pH, *pL;
    float *h2, *energy;
    cudaGetSymbolAddress((void**)&nH, g_nH);     cudaGetSymbolAddress((void**)&nL, g_nL);
    cudaGetSymbolAddress((void**)&qkvH, g_qkvH); cudaGetSymbolAddress((void**)&qkvL, g_qkvL);
    cudaGetSymbolAddress((void**)&vTH, g_vTH);   cudaGetSymbolAddress((void**)&vTL, g_vTL);
    cudaGetSymbolAddress((void**)&ctxH, g_ctxH); cudaGetSymbolAddress((void**)&ctxL, g_ctxL);
    cudaGetSymbolAddress((void**)&h2, g_h2);
    cudaGetSymbolAddress((void**)&x1H, g_x1H);   cudaGetSymbolAddress((void**)&x1L, g_x1L);
    cudaGetSymbolAddress((void**)&gH, g_gH);     cudaGetSymbolAddress((void**)&gL, g_gL);
    cudaGetSymbolAddress((void**)&wH, g_wH);     cudaGetSymbolAddress((void**)&wL, g_wL);
    cudaGetSymbolAddress((void**)&pH, g_pH);     cudaGetSymbolAddress((void**)&pL, g_pL);
    cudaGetSymbolAddress((void**)&energy, g_energy);

    cudaFuncSetAttribute(gemm_bf16s, cudaFuncAttributeMaxDynamicSharedMemorySize, GEMM_SMEM);

    const float inv_sqrt_hd = 0.08838834764831845f;
    const long DSQ = (long)DD * DD;
    __nv_bfloat16 *WoH = wH + 3*DSQ, *WoL = wL + 3*DSQ;
    __nv_bfloat16 *W1H = wH + 4*DSQ, *W1L = wL + 4*DSQ;
    __nv_bfloat16 *W2H = wH + 5*DSQ, *W2L = wL + 5*DSQ;
    __nv_bfloat16 *W3H = wH + 6*DSQ, *W3L = wL + 6*DSQ;

    // 0. ALL 7 weight transposes in ONE launch
    dim3 tgridW7(DD / 32, DD / 32, 7);
    transpose_split_w7<<<tgridW7, 256>>>(Wq, Wk, Wv, Wo, W1, W2, W3, wH, wL);

    dim3 gridDense(DD / GBN, MM / GBM, 1);
    dim3 gridQKV(DD / GBN, MM / GBM, 3);
    dim3 gridQK(TT / GBN, TT / GBM, BB * NHH);
    dim3 gridPV(1, TT / GBM, BB * NHH);

    // 1. norm1
    rmsnorm_split<<<MM, 256>>>(x, scale1, nH, nL);

    // 2. Q/K/V projections in ONE launch
    gemm_bf16s<<<gridQKV, GTHREADS, GEMM_SMEM>>>(nH, nL, wH, wL, bq, bk, bv, nullptr,
        nullptr, nullptr,
        nullptr, qkvH, qkvL, DD, DD, DD, DD,
        0, 0, 0, DSQ, 0, ELEMS, 3, 1.0f, EPI_SPLIT);

    // 3. vT split: [b,h][d][t] from V slice (z=2)
    dim3 tgridV(HDD / 32, TT / 32, BB * NHH);
    transpose_split_bf2<<<tgridV, 256>>>(qkvH + 2*ELEMS, qkvL + 2*ELEMS, vTH, vTL,
        DD, TT,
        (long)TT * DD, (long)HDD,
        (long)NHH * HDD * TT, (long)HDD * TT, NHH);

    // 4. energy = Q K^T / sqrt(HD)  (fp32)
    gemm_bf16s<<<gridQK, GTHREADS, GEMM_SMEM>>>(qkvH, qkvL, qkvH + ELEMS, qkvL + ELEMS,
        nullptr, nullptr, nullptr, nullptr,
        nullptr, nullptr,
        energy, nullptr, nullptr,
        HDD, DD, DD, TT,
        (long)TT * DD, (long)HDD,
        (long)TT * DD, (long)HDD,
        (long)NHH * TT * TT, (long)TT * TT,
        NHH, inv_sqrt_hd, EPI_C);

    // 5. softmax -> split probs
    softmax_split<<<BB * NHH * TT, 256>>>(energy, pH, pL);

    // 6. ctx = P @ V
    gemm_bf16s<<<gridPV, GTHREADS, GEMM_SMEM>>>(pH, pL, vTH, vTL,
        nullptr, nullptr, nullptr, nullptr,
        nullptr, nullptr,
        nullptr, ctxH, ctxL,
        TT, TT, TT, DD,
        (long)NHH * TT * TT, (long)TT * TT,
        (long)NHH * HDD * TT, (long)HDD * TT,
        (long)TT * DD, (long)HDD,
        NHH, 1.0f, EPI_SPLIT);

    // 7. h2 = ctx @ Wo + bo + x
    gemm_bf16s<<<gridDense, GTHREADS, GEMM_SMEM>>>(ctxH, ctxL, WoH, WoL, bo, nullptr, nullptr, x,
        nullptr, nullptr,
        h2, nullptr, nullptr, DD, DD, DD, DD, 0,0,0,0,0,0, 1, 1.0f, EPI_C);

    // 8. norm2
    rmsnorm_split<<<MM, 256>>>(h2, scale2, nH, nL);

    // 9. x1 = norm @ W1 (split only — no fp32 round-trip)
    gemm_bf16s<<<gridDense, GTHREADS, GEMM_SMEM>>>(nH, nL, W1H, W1L, nullptr, nullptr, nullptr, nullptr,
        nullptr, nullptr,
        nullptr, x1H, x1L, DD, DD, DD, DD, 0,0,0,0,0,0, 1, 1.0f, EPI_SPLIT);

    // 10+11. x2 = x1 @ W2 with fused swiglu (x1 reconstructed from split): g -> split
    gemm_bf16s<<<gridDense, GTHREADS, GEMM_SMEM>>>(x1H, x1L, W2H, W2L, nullptr, nullptr, nullptr, nullptr,
        x1H, x1L,
        nullptr, gH, gL, DD, DD, DD, DD, 0,0,0,0,0,0, 1, 1.0f, EPI_SWIGLU | EPI_SPLIT);

    // 12. out = g @ W3 + x
    gemm_bf16s<<<gridDense, GTHREADS, GEMM_SMEM>>>(gH, gL, W3H, W3L, nullptr, nullptr, nullptr, x,
        nullptr, nullptr,
        out, nullptr, nullptr, DD, DD, DD, DD, 0,0,0,0,0,0, 1, 1.0f, EPI_C);
}